// round 15
// baseline (speedup 1.0000x reference)
#include <cuda_runtime.h>
#include <cuda_bf16.h>
#include <math.h>
#include <stdint.h>

// ---------------- problem constants ----------------
#define DD     3584
#define BATCH  2
#define LL     256
#define BL     512      // BATCH*LL
#define NST    64       // ssm state dim
#define MM     64       // latent vectors
#define CONDD  256
#define KDIM   3584

// ---------------- scratch (device globals; no allocation) ----------------
__device__ float g_x    [BL*DD];
__device__ float g_xn   [BL*DD];
__device__ float g_dt   [BL*DD];
__device__ float g_keys [BL*DD];
__device__ float g_vals [BL*DD];
__device__ float g_xo   [BL*DD];
__device__ float g_BC   [BL*128];
__device__ float g_mean [BATCH*DD];
__device__ float g_c1   [BATCH*CONDD];
__device__ float g_scores[BATCH*MM*LL];
__device__ float g_part [2*16*MM*LL];
__device__ float g_z0p  [8*BATCH*MM*DD];
// bf16 split buffers (all weights pre-split once per call)
__device__ __nv_bfloat16 g_ipwh[DD*KDIM];
__device__ __nv_bfloat16 g_ipwl[DD*KDIM];
__device__ __nv_bfloat16 g_w2hi[2*3712*KDIM];  // [dtw|Bw|Cw] x 2 layers
__device__ __nv_bfloat16 g_w2lo[2*3712*KDIM];
__device__ __nv_bfloat16 g_w1hi[7168*KDIM];    // [pkw|pvw]
__device__ __nv_bfloat16 g_w1lo[7168*KDIM];
__device__ __nv_bfloat16 g_ahi [BL*DD];
__device__ __nv_bfloat16 g_alo [BL*DD];

__device__ __forceinline__ __nv_bfloat16 bits_to_bf16(unsigned short s) {
    __nv_bfloat16_raw r; r.x = s; return __nv_bfloat16(r);
}

// ---------------- shared GEMM helpers ----------------
#define KC      64
#define NCHUNK  (KDIM/KC)    // 56
#define BPITCH  144
#define GTHR    512

__device__ __forceinline__ void cp16(uint32_t saddr, const void* g) {
    asm volatile("cp.async.cg.shared.global [%0], [%1], 16;" :: "r"(saddr), "l"(g));
}
__device__ __forceinline__ uint32_t smem_u32(const void* p) {
    uint32_t a;
    asm("{ .reg .u64 t; cvta.to.shared.u64 t, %1; cvt.u32.u64 %0, t; }"
        : "=r"(a) : "l"(p));
    return a;
}
__device__ __forceinline__ void mma_bf16(float* c, const uint32_t* a, const uint32_t* b) {
    asm volatile(
        "mma.sync.aligned.m16n8k16.row.col.f32.bf16.bf16.f32 "
        "{%0,%1,%2,%3}, {%4,%5,%6,%7}, {%8,%9}, {%0,%1,%2,%3};"
        : "+f"(c[0]), "+f"(c[1]), "+f"(c[2]), "+f"(c[3])
        : "r"(a[0]), "r"(a[1]), "r"(a[2]), "r"(a[3]), "r"(b[0]), "r"(b[1]));
}
#define LDSM_X4(r, addr) asm volatile( \
    "ldmatrix.sync.aligned.m8n8.x4.shared.b16 {%0,%1,%2,%3}, [%4];" \
    : "=r"((r)[0]), "=r"((r)[1]), "=r"((r)[2]), "=r"((r)[3]) : "r"(addr))

// =====================================================================
// bf16x3 GEMM, 128x128 tile (round-11 design): ip / dtBC path
// =====================================================================
#define TM      128
#define TILEB   (128*BPITCH)          // 18432
#define STG     (4*TILEB)             // 73728
#define SMEM_GEMM (3*STG)             // 221184

__device__ __forceinline__ void fill_stage(uint32_t sbase, int s,
        const __nv_bfloat16* __restrict__ Ah, const __nv_bfloat16* __restrict__ Al,
        const __nv_bfloat16* __restrict__ Wh, const __nv_bfloat16* __restrict__ Wl,
        int bm, int bn, int chunk, int tid) {
    uint32_t st = sbase + s * STG;
    const int k0 = chunk * KC;
    #pragma unroll
    for (int i = 0; i < 2; i++) {
        int idx = tid + i * GTHR, r = idx >> 3, j = idx & 7;
        uint32_t d = st + r * BPITCH + j * 16;
        size_t ga = (size_t)(bm + r) * KDIM + k0 + j * 8;
        size_t gw = (size_t)(bn + r) * KDIM + k0 + j * 8;
        cp16(d,             Ah + ga);
        cp16(d + TILEB,     Al + ga);
        cp16(d + 2 * TILEB, Wh + gw);
        cp16(d + 3 * TILEB, Wl + gw);
    }
}

// ACT: 0 = none, 1 = softplus (C1 tiles only)
template<int ACT>
__global__ void __launch_bounds__(GTHR, 1)
bf16_gemm(const __nv_bfloat16* __restrict__ Ah, const __nv_bfloat16* __restrict__ Al,
          const __nv_bfloat16* __restrict__ Wh, const __nv_bfloat16* __restrict__ Wl,
          const float* __restrict__ bias, float* __restrict__ C1,
          float* __restrict__ C2, int nsplitTiles, int c2s) {
    extern __shared__ char smc[];
    uint32_t sbase = smem_u32(smc);
    const int tid = threadIdx.x;
    const int wid = tid >> 5, lane = tid & 31;
    const int wm = wid >> 2, wn = wid & 3;
    const int g = lane >> 2, tg = lane & 3;
    const int bm = blockIdx.y * TM, bn = blockIdx.x * 128;

    const int q = lane >> 3, rr = lane & 7;
    const uint32_t offA = (uint32_t)((wm * 32 + rr + (q & 1) * 8) * BPITCH + (q >> 1) * 16);
    const uint32_t offB = (uint32_t)(2 * TILEB +
        (wn * 32 + (q >> 1) * 8 + rr) * BPITCH + (q & 1) * 16);

    float acc[2][4][4];
    #pragma unroll
    for (int i = 0; i < 2; i++)
        #pragma unroll
        for (int j = 0; j < 4; j++)
            #pragma unroll
            for (int k = 0; k < 4; k++) acc[i][j][k] = 0.f;

    fill_stage(sbase, 0, Ah, Al, Wh, Wl, bm, bn, 0, tid);
    asm volatile("cp.async.commit_group;" ::: "memory");
    fill_stage(sbase, 1, Ah, Al, Wh, Wl, bm, bn, 1, tid);
    asm volatile("cp.async.commit_group;" ::: "memory");

    int s = 0;
    for (int c = 0; c < NCHUNK; c++) {
        asm volatile("cp.async.wait_group 1;" ::: "memory");
        __syncthreads();
        int pn = c + 2;
        if (pn < NCHUNK) {
            int sp = s + 2; if (sp >= 3) sp -= 3;
            fill_stage(sbase, sp, Ah, Al, Wh, Wl, bm, bn, pn, tid);
        }
        asm volatile("cp.async.commit_group;" ::: "memory");

        const uint32_t base = sbase + s * STG;
        #pragma unroll
        for (int ks = 0; ks < 4; ks++) {
            const uint32_t kb = ks * 32;
            uint32_t ah[2][4], al[2][4], bh[4][2], bl[4][2];
            #pragma unroll
            for (int mi = 0; mi < 2; mi++) {
                uint32_t ad = base + offA + mi * (16 * BPITCH) + kb;
                LDSM_X4(ah[mi], ad);
                LDSM_X4(al[mi], ad + TILEB);
            }
            #pragma unroll
            for (int p = 0; p < 2; p++) {
                uint32_t bd = base + offB + p * (16 * BPITCH) + kb;
                LDSM_X4(&bh[2 * p][0], bd);
                LDSM_X4(&bl[2 * p][0], bd + TILEB);
            }
            #pragma unroll
            for (int mi = 0; mi < 2; mi++)
                #pragma unroll
                for (int nj = 0; nj < 4; nj++)
                    mma_bf16(acc[mi][nj], ah[mi], bh[nj]);
            #pragma unroll
            for (int mi = 0; mi < 2; mi++)
                #pragma unroll
                for (int nj = 0; nj < 4; nj++)
                    mma_bf16(acc[mi][nj], al[mi], bh[nj]);
            #pragma unroll
            for (int mi = 0; mi < 2; mi++)
                #pragma unroll
                for (int nj = 0; nj < 4; nj++)
                    mma_bf16(acc[mi][nj], ah[mi], bl[nj]);
        }
        s++; if (s >= 3) s = 0;
    }

    const bool first = ((int)blockIdx.x < nsplitTiles);
    float* Cb = first ? C1 : C2;
    const int colb = first ? bn : (bn - nsplitTiles * 128);
    const int strd = first ? DD : c2s;
    const bool ub = first && (bias != nullptr);
    #pragma unroll
    for (int mi = 0; mi < 2; mi++) {
        #pragma unroll
        for (int nj = 0; nj < 4; nj++) {
            int m = bm + wm * 32 + mi * 16 + g;
            int nl = colb + wn * 32 + nj * 8 + tg * 2;
            float v0 = acc[mi][nj][0], v1 = acc[mi][nj][1];
            float v2 = acc[mi][nj][2], v3 = acc[mi][nj][3];
            if (ub) {
                float b0 = bias[nl], b1 = bias[nl + 1];
                v0 += b0; v1 += b1; v2 += b0; v3 += b1;
            }
            if (ACT == 1 && first) {
                v0 = fmaxf(v0, 0.f) + log1pf(__expf(-fabsf(v0)));
                v1 = fmaxf(v1, 0.f) + log1pf(__expf(-fabsf(v1)));
                v2 = fmaxf(v2, 0.f) + log1pf(__expf(-fabsf(v2)));
                v3 = fmaxf(v3, 0.f) + log1pf(__expf(-fabsf(v3)));
            }
            *(float2*)&Cb[(size_t)m * strd + nl]       = make_float2(v0, v1);
            *(float2*)&Cb[(size_t)(m + 8) * strd + nl] = make_float2(v2, v3);
        }
    }
}

// =====================================================================
// bf16x3 GEMM, 256x128 tile, 2-stage: pkv path (single-wave 112 CTAs)
// =====================================================================
#define BATILE (256*BPITCH)           // 36864
#define BWTILE (128*BPITCH)           // 18432
#define BSTG   (2*BATILE + 2*BWTILE)  // 110592
#define SMEM_BIG (2*BSTG)             // 221184

__device__ __forceinline__ void fill_big(uint32_t sbase, int s,
        const __nv_bfloat16* __restrict__ Ah, const __nv_bfloat16* __restrict__ Al,
        const __nv_bfloat16* __restrict__ Wh, const __nv_bfloat16* __restrict__ Wl,
        int bm, int bn, int chunk, int tid) {
    uint32_t st = sbase + s * BSTG;
    const int k0 = chunk * KC;
    #pragma unroll
    for (int i = 0; i < 4; i++) {       // A: 256 rows x 8
        int idx = tid + i * GTHR, r = idx >> 3, j = idx & 7;
        uint32_t d = st + r * BPITCH + j * 16;
        size_t ga = (size_t)(bm + r) * KDIM + k0 + j * 8;
        cp16(d,          Ah + ga);
        cp16(d + BATILE, Al + ga);
    }
    #pragma unroll
    for (int i = 0; i < 2; i++) {       // W: 128 rows x 8
        int idx = tid + i * GTHR, r = idx >> 3, j = idx & 7;
        uint32_t d = st + 2 * BATILE + r * BPITCH + j * 16;
        size_t gw = (size_t)(bn + r) * KDIM + k0 + j * 8;
        cp16(d,          Wh + gw);
        cp16(d + BWTILE, Wl + gw);
    }
}

__global__ void __launch_bounds__(GTHR, 1)
bf16_gemm_big(const __nv_bfloat16* __restrict__ Ah, const __nv_bfloat16* __restrict__ Al,
              const __nv_bfloat16* __restrict__ Wh, const __nv_bfloat16* __restrict__ Wl,
              float* __restrict__ C1, float* __restrict__ C2,
              int nsplitTiles, int c2s) {
    extern __shared__ char smc[];
    uint32_t sbase = smem_u32(smc);
    const int tid = threadIdx.x;
    const int wid = tid >> 5, lane = tid & 31;
    const int wm = wid >> 2, wn = wid & 3;     // warp tile 64(m) x 32(n)
    const int g = lane >> 2, tg = lane & 3;
    const int bm = blockIdx.y * 256, bn = blockIdx.x * 128;

    const int q = lane >> 3, rr = lane & 7;
    const uint32_t offA = (uint32_t)((wm * 64 + rr + (q & 1) * 8) * BPITCH + (q >> 1) * 16);
    const uint32_t offB = (uint32_t)(2 * BATILE +
        (wn * 32 + (q >> 1) * 8 + rr) * BPITCH + (q & 1) * 16);

    float acc[4][4][4];
    #pragma unroll
    for (int i = 0; i < 4; i++)
        #pragma unroll
        for (int j = 0; j < 4; j++)
            #pragma unroll
            for (int k = 0; k < 4; k++) acc[i][j][k] = 0.f;

    fill_big(sbase, 0, Ah, Al, Wh, Wl, bm, bn, 0, tid);
    asm volatile("cp.async.commit_group;" ::: "memory");
    fill_big(sbase, 1, Ah, Al, Wh, Wl, bm, bn, 1, tid);
    asm volatile("cp.async.commit_group;" ::: "memory");

    for (int c = 0; c < NCHUNK; c++) {
        asm volatile("cp.async.wait_group 1;" ::: "memory");
        __syncthreads();

        const uint32_t base = sbase + (c & 1) * BSTG;
        #pragma unroll
        for (int ks = 0; ks < 4; ks++) {
            const uint32_t kb = ks * 32;
            uint32_t ah[4][4], al[4][4], bh[4][2], bl[4][2];
            #pragma unroll
            for (int mi = 0; mi < 4; mi++) {
                uint32_t ad = base + offA + mi * (16 * BPITCH) + kb;
                LDSM_X4(ah[mi], ad);
                LDSM_X4(al[mi], ad + BATILE);
            }
            #pragma unroll
            for (int p = 0; p < 2; p++) {
                uint32_t bd = base + offB + p * (16 * BPITCH) + kb;
                LDSM_X4(&bh[2 * p][0], bd);
                LDSM_X4(&bl[2 * p][0], bd + BWTILE);
            }
            #pragma unroll
            for (int mi = 0; mi < 4; mi++)
                #pragma unroll
                for (int nj = 0; nj < 4; nj++)
                    mma_bf16(acc[mi][nj], ah[mi], bh[nj]);
            #pragma unroll
            for (int mi = 0; mi < 4; mi++)
                #pragma unroll
                for (int nj = 0; nj < 4; nj++)
                    mma_bf16(acc[mi][nj], al[mi], bh[nj]);
            #pragma unroll
            for (int mi = 0; mi < 4; mi++)
                #pragma unroll
                for (int nj = 0; nj < 4; nj++)
                    mma_bf16(acc[mi][nj], ah[mi], bl[nj]);
        }
        __syncthreads();
        int pn = c + 2;
        if (pn < NCHUNK)
            fill_big(sbase, c & 1, Ah, Al, Wh, Wl, bm, bn, pn, tid);
        asm volatile("cp.async.commit_group;" ::: "memory");
    }

    const bool first = ((int)blockIdx.x < nsplitTiles);
    float* Cb = first ? C1 : C2;
    const int colb = first ? bn : (bn - nsplitTiles * 128);
    const int strd = first ? DD : c2s;
    #pragma unroll
    for (int mi = 0; mi < 4; mi++) {
        #pragma unroll
        for (int nj = 0; nj < 4; nj++) {
            int m = bm + wm * 64 + mi * 16 + g;
            int nl = colb + wn * 32 + nj * 8 + tg * 2;
            *(float2*)&Cb[(size_t)m * strd + nl] =
                make_float2(acc[mi][nj][0], acc[mi][nj][1]);
            *(float2*)&Cb[(size_t)(m + 8) * strd + nl] =
                make_float2(acc[mi][nj][2], acc[mi][nj][3]);
        }
    }
}

// ---------------- merged fp32 -> (hi, lo) bf16 split ----------------
__device__ __forceinline__ void split4(float4 f, uint2& hp, uint2& lp) {
    uint32_t u0 = __float_as_uint(f.x), u1 = __float_as_uint(f.y);
    uint32_t u2 = __float_as_uint(f.z), u3 = __float_as_uint(f.w);
    float h0 = __uint_as_float(u0 & 0xFFFF0000u);
    float h1 = __uint_as_float(u1 & 0xFFFF0000u);
    float h2 = __uint_as_float(u2 & 0xFFFF0000u);
    float h3 = __uint_as_float(u3 & 0xFFFF0000u);
    hp.x = __byte_perm(u0, u1, 0x7632);
    hp.y = __byte_perm(u2, u3, 0x7632);
    __nv_bfloat162 l0 = __floats2bfloat162_rn(f.x - h0, f.y - h1);
    __nv_bfloat162 l1 = __floats2bfloat162_rn(f.z - h2, f.w - h3);
    lp.x = *(uint32_t*)&l0;
    lp.y = *(uint32_t*)&l1;
}

#define N0Q (BL*DD/4)
#define N1Q (DD*KDIM/4)
#define N2Q (2*3712*KDIM/4)
#define N3Q (7168*KDIM/4)
#define NTQ (N0Q+N1Q+N2Q+N3Q)

__global__ void __launch_bounds__(256)
split_all(const float* __restrict__ tok, const float* __restrict__ ipw,
          const float* __restrict__ dtw, const float* __restrict__ Bw,
          const float* __restrict__ Cw, const float* __restrict__ pkw,
          const float* __restrict__ pvw,
          __nv_bfloat16* __restrict__ ah, __nv_bfloat16* __restrict__ al,
          __nv_bfloat16* __restrict__ iph, __nv_bfloat16* __restrict__ ipl,
          __nv_bfloat16* __restrict__ w2h, __nv_bfloat16* __restrict__ w2l,
          __nv_bfloat16* __restrict__ w1h, __nv_bfloat16* __restrict__ w1l) {
    long qd = (long)blockIdx.x * 256 + threadIdx.x;
    if (qd >= NTQ) return;
    const float* src;
    __nv_bfloat16 *dh, *dl;
    long e;
    if (qd < N0Q) {
        e = qd * 4; src = tok + e; dh = ah + e; dl = al + e;
    } else if (qd < N0Q + N1Q) {
        e = (qd - N0Q) * 4; src = ipw + e; dh = iph + e; dl = ipl + e;
    } else if (qd < N0Q + N1Q + N2Q) {
        e = (qd - N0Q - N1Q) * 4;
        int row = (int)(e / KDIM);
        int col = (int)(e - (long)row * KDIM);
        int layer = row / 3712, lr = row - layer * 3712;
        const float* s = (lr < 3584)
            ? dtw + (size_t)layer * DD * DD + (size_t)lr * KDIM
            : (lr < 3648)
            ? Bw + (size_t)layer * NST * DD + (size_t)(lr - 3584) * KDIM
            : Cw + (size_t)layer * NST * DD + (size_t)(lr - 3648) * KDIM;
        src = s + col; dh = w2h + e; dl = w2l + e;
    } else {
        e = (qd - N0Q - N1Q - N2Q) * 4;
        int row = (int)(e / KDIM);
        int col = (int)(e - (long)row * KDIM);
        const float* s = (row < 3584) ? pkw + (size_t)row * KDIM
                                      : pvw + (size_t)(row - 3584) * KDIM;
        src = s + col; dh = w1h + e; dl = w1l + e;
    }
    uint2 hp, lp;
    split4(*(const float4*)src, hp, lp);
    *(uint2*)dh = hp;
    *(uint2*)dl = lp;
}

// ---------------- reductions ----------------
__device__ __forceinline__ float blockReduceSum(float v, float* red) {
    int lane = threadIdx.x & 31, w = threadIdx.x >> 5;
    #pragma unroll
    for (int o = 16; o; o >>= 1) v += __shfl_xor_sync(0xffffffffu, v, o);
    if (lane == 0) red[w] = v;
    __syncthreads();
    float t = (threadIdx.x < 8) ? red[threadIdx.x] : 0.f;
    if (w == 0) {
        #pragma unroll
        for (int o = 4; o; o >>= 1) t += __shfl_xor_sync(0xffffffffu, t, o);
        if (lane == 0) red[0] = t;
    }
    __syncthreads();
    float r = red[0];
    __syncthreads();
    return r;
}
__device__ __forceinline__ float blockReduceMax(float v, float* red) {
    int lane = threadIdx.x & 31, w = threadIdx.x >> 5;
    #pragma unroll
    for (int o = 16; o; o >>= 1) v = fmaxf(v, __shfl_xor_sync(0xffffffffu, v, o));
    if (lane == 0) red[w] = v;
    __syncthreads();
    float t = (threadIdx.x < 8) ? red[threadIdx.x] : -3.4e38f;
    if (w == 0) {
        #pragma unroll
        for (int o = 4; o; o >>= 1) t = fmaxf(t, __shfl_xor_sync(0xffffffffu, t, o));
        if (lane == 0) red[0] = t;
    }
    __syncthreads();
    float r = red[0];
    __syncthreads();
    return r;
}

// ---------------- layernorm with fused bf16 split ----------------
__global__ void __launch_bounds__(256)
ln_split(const float* __restrict__ x, const float* __restrict__ g,
         const float* __restrict__ bta, float* __restrict__ out,
         __nv_bfloat16* __restrict__ hi, __nv_bfloat16* __restrict__ lo) {
    __shared__ float red[8];
    int row = blockIdx.x, tid = threadIdx.x;
    const float* xr = x + (size_t)row * DD;
    float v[14];
    float s = 0.f;
    #pragma unroll
    for (int i = 0; i < 14; i++) { v[i] = xr[tid + i * 256]; s += v[i]; }
    s = blockReduceSum(s, red);
    float mu = s * (1.f / DD);
    float q = 0.f;
    #pragma unroll
    for (int i = 0; i < 14; i++) { float d = v[i] - mu; q += d * d; }
    q = blockReduceSum(q, red);
    float rstd = rsqrtf(q * (1.f / DD) + 1e-5f);
    #pragma unroll
    for (int i = 0; i < 14; i++) {
        int c = tid + i * 256;
        float o = (v[i] - mu) * rstd * g[c] + bta[c];
        size_t off = (size_t)row * DD + c;
        out[off] = o;
        uint32_t u = __float_as_uint(o);
        float hf = __uint_as_float(u & 0xFFFF0000u);
        hi[off] = bits_to_bf16((unsigned short)(u >> 16));
        lo[off] = __float2bfloat16(o - hf);
    }
}

// ---------------- selective scan: BC via smem, 8-iter chunks -------
#define SCD 56
#define SCH 8
__global__ void __launch_bounds__(SCD*4)
scan_kernel(const float* __restrict__ xn, const float* __restrict__ dt,
            const float* __restrict__ BC, const float* __restrict__ Alog,
            const float* __restrict__ Dvec, float* __restrict__ x) {
    __shared__ float sBC[2][SCH][128];
    const int b   = blockIdx.y;
    const int tid = threadIdx.x;
    const int d   = blockIdx.x * SCD + (tid >> 2);
    const int ns  = tid & 3;
    float h[16], Aa[16];
    #pragma unroll
    for (int j = 0; j < 16; j++) {
        h[j]  = 0.f;
        Aa[j] = -__expf(Alog[(size_t)d * NST + ns * 16 + j]);
    }
    const float Dv = Dvec[d];
    const float* dtp = dt + (size_t)b * LL * DD + d;
    const float* xnp = xn + (size_t)b * LL * DD + d;
    float*       xp  = x  + (size_t)b * LL * DD + d;
    const float* BCrow = BC + (size_t)b * LL * 128;

    const uint32_t sb = smem_u32(sBC);
    for (int idx = tid; idx < SCH * 32; idx += SCD * 4) {
        int row = idx >> 5, qq = idx & 31;
        cp16(sb + (uint32_t)(row * 128 + qq * 4) * 4,
             BCrow + (size_t)row * 128 + qq * 4);
    }
    asm volatile("cp.async.commit_group;" ::: "memory");

    float dtv = dtp[0], xv = xnp[0], xo = xp[0];

    for (int ch = 0; ch < LL / SCH; ch++) {
        const int buf = ch & 1;
        if (ch + 1 < LL / SCH) {
            const int l0 = (ch + 1) * SCH;
            const uint32_t db = sb + (uint32_t)((buf ^ 1) * SCH * 128) * 4;
            for (int idx = tid; idx < SCH * 32; idx += SCD * 4) {
                int row = idx >> 5, qq = idx & 31;
                cp16(db + (uint32_t)(row * 128 + qq * 4) * 4,
                     BCrow + (size_t)(l0 + row) * 128 + qq * 4);
            }
        }
        asm volatile("cp.async.commit_group;" ::: "memory");
        asm volatile("cp.async.wait_group 1;" ::: "memory");
        __syncthreads();

        const float* sc = &sBC[buf][0][0];
        #pragma unroll
        for (int li = 0; li < SCH; li++) {
            const int l = ch * SCH + li;
            float dtn = 0.f, xnn = 0.f, xon = 0.f;
            if (l + 1 < LL) {
                size_t o = (size_t)(l + 1) * DD;
                dtn = dtp[o]; xnn = xnp[o]; xon = xp[o];
            }
            const float4* Bp = (const float4*)(sc + li * 128 + ns * 16);
            const float4* Cp = (const float4*)(sc + li * 128 + 64 + ns * 16);
            float t = dtv * xv;
            float y = 0.f;
            #pragma unroll
            for (int qq = 0; qq < 4; qq++) {
                float4 Bv = Bp[qq];
                float4 Cv = Cp[qq];
                float* hq = h + qq * 4;
                const float* Aq = Aa + qq * 4;
                hq[0] = fmaf(__expf(dtv * Aq[0]), hq[0], Bv.x * t);
                hq[1] = fmaf(__expf(dtv * Aq[1]), hq[1], Bv.y * t);
                hq[2] = fmaf(__expf(dtv * Aq[2]), hq[2], Bv.z * t);
                hq[3] = fmaf(__expf(dtv * Aq[3]), hq[3], Bv.w * t);
                y += Cv.x * hq[0] + Cv.y * hq[1] + Cv.z * hq[2] + Cv.w * hq[3];
            }
            y += __shfl_xor_sync(0xffffffffu, y, 1);
            y += __shfl_xor_sync(0xffffffffu, y, 2);
            if (ns == 0) xp[(size_t)l * DD] = fmaf(Dv, xo, y);
            dtv = dtn; xv = xnn; xo = xon;
        }
        __syncthreads();
    }
}

// ---------------- attention scores: split-K, both batches ----------------
__global__ void __launch_bounds__(128)
attn_scores(const float* __restrict__ A, const float* __restrict__ keys,
            float* __restrict__ part) {
    __shared__ float As[16][64];
    __shared__ float Ws[16][128];
    const int tid = threadIdx.x;
    const int bn = blockIdx.x * 128;
    const int bat = blockIdx.y;
    const int kbase = blockIdx.z * (KDIM / 16);
    const float* W = keys + (size_t)bat * LL * KDIM;
    const int lr = tid >> 2;
    const int lk = (tid & 3) << 2;
    const int tx = tid & 15;
    const int ty = tid >> 4;
    float acc[8][8];
    #pragma unroll
    for (int i = 0; i < 8; i++)
        #pragma unroll
        for (int j = 0; j < 8; j++) acc[i][j] = 0.f;

    for (int k0 = kbase; k0 < kbase + KDIM / 16; k0 += 16) {
        {
            int r = lr;
            float4 v = *(const float4*)(A + (size_t)r * KDIM + k0 + lk);
            As[lk + 0][r] = v.x; As[lk + 1][r] = v.y;
            As[lk + 2][r] = v.z; As[lk + 3][r] = v.w;
            r = lr + 32;
            v = *(const float4*)(A + (size_t)r * KDIM + k0 + lk);
            As[lk + 0][r] = v.x; As[lk + 1][r] = v.y;
            As[lk + 2][r] = v.z; As[lk + 3][r] = v.w;
        }
        #pragma unroll
        for (int hh = 0; hh < 4; hh++) {
            int r = lr + hh * 32;
            float4 v = *(const float4*)(W + (size_t)(bn + r) * KDIM + k0 + lk);
            Ws[lk + 0][r] = v.x; Ws[lk + 1][r] = v.y;
            Ws[lk + 2][r] = v.z; Ws[lk + 3][r] = v.w;
        }
        __syncthreads();
        #pragma unroll
        for (int kk = 0; kk < 16; kk++) {
            float a[8], w[8];
            *(float4*)(a)     = *(const float4*)&As[kk][ty * 8];
            *(float4*)(a + 4) = *(const float4*)&As[kk][ty * 8 + 4];
            *(float4*)(w)     = *(const float4*)&Ws[kk][tx * 8];
            *(float4*)(w + 4) = *(const float4*)&Ws[kk][tx * 8 + 4];
            #pragma unroll
            for (int i = 0; i < 8; i++)
                #pragma unroll
                for (int j = 0; j < 8; j++)
                    acc[i][j] = fmaf(a[i], w[j], acc[i][j]);
        }
        __syncthreads();
    }
    float* outp = part + (size_t)bat * 16 * MM * LL + (size_t)blockIdx.z * MM * LL;
    #pragma unroll
    for (int i = 0; i < 8; i++) {
        int row = ty * 8 + i;
        #pragma unroll
        for (int j4 = 0; j4 < 2; j4++) {
            float4 o = make_float4(acc[i][j4*4+0], acc[i][j4*4+1],
                                   acc[i][j4*4+2], acc[i][j4*4+3]);
            *(float4*)&outp[(size_t)row * LL + bn + tx * 8 + j4 * 4] = o;
        }
    }
}

// fused: sum 16 split-K partials, scale, softmax over 256 cols
__global__ void __launch_bounds__(256)
attn_softmax(const float* __restrict__ part, float* __restrict__ scores,
             float scal) {
    __shared__ float red[8];
    int bx = blockIdx.x;
    int b = bx >> 6, m = bx & 63;
    int l = threadIdx.x;
    const float* p = part + (size_t)b * 16 * MM * LL + (size_t)m * LL + l;
    float s = 0.f;
    #pragma unroll
    for (int z = 0; z < 16; z++) s += p[(size_t)z * MM * LL];
    float v = s * scal;
    float mx = blockReduceMax(v, red);
    float e = __expf(v - mx);
    float sum = blockReduceSum(e, red);
    scores[(size_t)bx * LL + l] = e / sum;
}

// ---------------- mean over L ----------------
__global__ void meanL(const float* __restrict__ xo, float* __restrict__ mean) {
    int idx = blockIdx.x * 256 + threadIdx.x;
    int b = idx / DD, d = idx % DD;
    float s = 0.f;
    for (int l = 0; l < LL; l++) s += xo[(size_t)(b * LL + l) * DD + d];
    mean[idx] = s * (1.f / LL);
}

// ---------------- warp-per-output dot (cond path) ----------
template<int ACT>
__global__ void rowdot(const float* __restrict__ A, const float* __restrict__ W,
                       const float* __restrict__ bias, float* __restrict__ out,
                       int rows, int cols, int K) {
    int gw = (blockIdx.x * blockDim.x + threadIdx.x) >> 5;
    int lane = threadIdx.x & 31;
    if (gw >= rows * cols) return;
    int r = gw / cols, c = gw % cols;
    const float4* a = (const float4*)(A + (size_t)r * K);
    const float4* w = (const float4*)(W + (size_t)c * K);
    int K4 = K >> 2;
    float s = 0.f;
    for (int k = lane; k < K4; k += 32) {
        float4 x = a[k], y = w[k];
        s += x.x * y.x + x.y * y.y + x.z * y.z + x.w * y.w;
    }
    #pragma unroll
    for (int o = 16; o; o >>= 1) s += __shfl_xor_sync(0xffffffffu, s, o);
    if (lane == 0) {
        s += bias[c];
        if (ACT == 2) s = s / (1.f + __expf(-s));
        out[(size_t)r * cols + c] = s;
    }
}

// ---------------- z0 = attn @ values ----------------
__global__ void __launch_bounds__(256)
z0_partial(const float* __restrict__ attn, const float* __restrict__ vals,
           float* __restrict__ part) {
    int d  = blockIdx.x * 256 + threadIdx.x;
    int b  = blockIdx.y;
    int sp = blockIdx.z;
    __shared__ float sa[64][32];
    int l0 = sp * 32;
    for (int i = threadIdx.x; i < 2048; i += 256) {
        int m = i >> 5, li = i & 31;
        sa[m][li] = attn[(size_t)(b * MM + m) * LL + l0 + li];
    }
    __syncthreads();
    float acc[64];
    #pragma unroll
    for (int m = 0; m < 64; m++) acc[m] = 0.f;
    for (int li = 0; li < 32; li += 4) {
        float v0 = vals[(size_t)(b * LL + l0 + li + 0) * DD + d];
        float v1 = vals[(size_t)(b * LL + l0 + li + 1) * DD + d];
        float v2 = vals[(size_t)(b * LL + l0 + li + 2) * DD + d];
        float v3 = vals[(size_t)(b * LL + l0 + li + 3) * DD + d];
        #pragma unroll
        for (int m = 0; m < 64; m++) {
            float4 a4 = *(const float4*)&sa[m][li];
            acc[m] = fmaf(a4.x, v0, fmaf(a4.y, v1, fmaf(a4.z, v2, fmaf(a4.w, v3, acc[m]))));
        }
    }
    #pragma unroll
    for (int m = 0; m < 64; m++)
        part[((size_t)(sp * BATCH + b) * MM + m) * DD + d] = acc[m];
}

__global__ void z0_reduce(const float* __restrict__ part, float* __restrict__ out) {
    int i = blockIdx.x * 256 + threadIdx.x;
    float s = 0.f;
    #pragma unroll
    for (int z = 0; z < 8; z++) s += part[(size_t)z * (BATCH * MM * DD) + i];
    out[i] = s;
}

// ---------------- host side ----------------
extern "C" void kernel_launch(void* const* d_in, const int* in_sizes, int n_in,
                              void* d_out, int out_size) {
    const float* tok  = (const float*)d_in[0];
    const float* ipw  = (const float*)d_in[1];
    const float* ipb  = (const float*)d_in[2];
    const float* ng   = (const float*)d_in[3];
    const float* nb   = (const float*)d_in[4];
    const float* dtw  = (const float*)d_in[5];
    const float* dtb  = (const float*)d_in[6];
    const float* Bw   = (const float*)d_in[7];
    const float* Cw   = (const float*)d_in[8];
    const float* Dvv  = (const float*)d_in[9];
    const float* Alog = (const float*)d_in[10];
    const float* og   = (const float*)d_in[11];
    const float* ob   = (const float*)d_in[12];
    const float* lq   = (const float*)d_in[13];
    const float* pkw  = (const float*)d_in[14];
    const float* pvw  = (const float*)d_in[15];
    const float* w1   = (const float*)d_in[16];
    const float* b1   = (const float*)d_in[17];
    const float* w2   = (const float*)d_in[18];
    const float* b2   = (const float*)d_in[19];
    float* out = (float*)d_out;

    float *px, *pxn, *pdt, *pkeys, *pvals, *pxo, *pBC, *pmean, *pc1, *pscores, *ppart, *pz0p;
    __nv_bfloat16 *piph, *pipl, *pw2h, *pw2l, *pw1h, *pw1l, *pah, *pal;
    cudaGetSymbolAddress((void**)&px,     g_x);
    cudaGetSymbolAddress((void**)&pxn,    g_xn);
    cudaGetSymbolAddress((void**)&pdt,    g_dt);
    cudaGetSymbolAddress((void**)&pkeys,  g_keys);
    cudaGetSymbolAddress((void**)&pvals,  g_vals);
    cudaGetSymbolAddress((void**)&pxo,    g_xo);
    cudaGetSymbolAddress((void**)&pBC,    g_BC);
    cudaGetSymbolAddress((void**)&pmean,  g_mean);
    cudaGetSymbolAddress((void**)&pc1,    g_c1);
    cudaGetSymbolAddress((void**)&pscores,g_scores);
    cudaGetSymbolAddress((void**)&ppart,  g_part);
    cudaGetSymbolAddress((void**)&pz0p,   g_z0p);
    cudaGetSymbolAddress((void**)&piph,   g_ipwh);
    cudaGetSymbolAddress((void**)&pipl,   g_ipwl);
    cudaGetSymbolAddress((void**)&pw2h,   g_w2hi);
    cudaGetSymbolAddress((void**)&pw2l,   g_w2lo);
    cudaGetSymbolAddress((void**)&pw1h,   g_w1hi);
    cudaGetSymbolAddress((void**)&pw1l,   g_w1lo);
    cudaGetSymbolAddress((void**)&pah,    g_ahi);
    cudaGetSymbolAddress((void**)&pal,    g_alo);

    cudaFuncSetAttribute(bf16_gemm<0>, cudaFuncAttributeMaxDynamicSharedMemorySize, SMEM_GEMM);
    cudaFuncSetAttribute(bf16_gemm<1>, cudaFuncAttributeMaxDynamicSharedMemorySize, SMEM_GEMM);
    cudaFuncSetAttribute(bf16_gemm_big, cudaFuncAttributeMaxDynamicSharedMemorySize, SMEM_BIG);

    // one merged split for ALL weights + token activations
    split_all<<<(int)((NTQ + 255) / 256), 256>>>(tok, ipw, dtw, Bw, Cw, pkw, pvw,
                                                 pah, pal, piph, pipl,
                                                 pw2h, pw2l, pw1h, pw1l);
    // input projection
    bf16_gemm<0><<<dim3(28, 4), GTHR, SMEM_GEMM>>>(pah, pal, piph, pipl,
                                                   ipb, px, nullptr, 28, 0);
    // layer 0
    ln_split<<<BL, 256>>>(px, ng, nb, pxn, pah, pal);
    bf16_gemm<1><<<dim3(29, 4), GTHR, SMEM_GEMM>>>(pah, pal, pw2h, pw2l,
                                                   dtb, pdt, pBC, 28, 128);
    scan_kernel<<<dim3(DD / SCD, BATCH), SCD * 4>>>(pxn, pdt, pBC, Alog, Dvv, px);
    // layer 1
    ln_split<<<BL, 256>>>(px, ng + DD, nb + DD, pxn, pah, pal);
    bf16_gemm<1><<<dim3(29, 4), GTHR, SMEM_GEMM>>>(pah, pal,
                                                   pw2h + (size_t)3712 * KDIM,
                                                   pw2l + (size_t)3712 * KDIM,
                                                   dtb + DD, pdt, pBC, 28, 128);
    scan_kernel<<<dim3(DD / SCD, BATCH), SCD * 4>>>(pxn, pdt, pBC,
                                                    Alog + (size_t)DD * NST,
                                                    Dvv + DD, px);
    // output norm (+ split for pooling GEMM)
    ln_split<<<BL, 256>>>(px, og, ob, pxo, pah, pal);

    // conditioning head
    meanL<<<(BATCH * DD) / 256, 256>>>(pxo, pmean);
    rowdot<2><<<(BATCH * CONDD * 32 + 255) / 256, 256>>>(pmean, w1, b1, pc1, BATCH, CONDD, DD);
    rowdot<0><<<(BATCH * CONDD * 32 + 255) / 256, 256>>>(pc1, w2, b2, out + BATCH * MM * DD,
                                                         BATCH, CONDD, CONDD);

    // fused pool_k | pool_v projection: 256x128 tiles, single wave
    bf16_gemm_big<<<dim3(56, 2), GTHR, SMEM_BIG>>>(pah, pal, pw1h, pw1l,
                                                   pkeys, pvals, 28, DD);

    // attention: one launch covering both batches, then fused reduce+softmax
    attn_scores<<<dim3(LL / 128, BATCH, 16), 128>>>(lq, pkeys, ppart);
    attn_softmax<<<BATCH * MM, 256>>>(ppart, pscores, 1.f / sqrtf((float)DD));

    // z0 = attn @ values
    z0_partial<<<dim3(DD / 256, BATCH, 8), 256>>>(pscores, pvals, pz0p);
    z0_reduce<<<(BATCH * MM * DD) / 256, 256>>>(pz0p, out);
}

// round 16
// speedup vs baseline: 1.0021x; 1.0021x over previous
#include <cuda_runtime.h>
#include <cuda_bf16.h>
#include <math.h>
#include <stdint.h>

// ---------------- problem constants ----------------
#define DD     3584
#define BATCH  2
#define LL     256
#define BL     512      // BATCH*LL
#define NST    64       // ssm state dim
#define MM     64       // latent vectors
#define CONDD  256
#define KDIM   3584

// ---------------- scratch (device globals; no allocation) ----------------
__device__ float g_x    [BL*DD];
__device__ float g_xn   [BL*DD];
__device__ float g_dt   [BL*DD];
__device__ float g_keys [BL*DD];
__device__ float g_vals [BL*DD];
__device__ float g_xo   [BL*DD];
__device__ float g_BC   [BL*128];
__device__ float g_mean [BATCH*DD];
__device__ float g_c1   [BATCH*CONDD];
__device__ float g_scores[BATCH*MM*LL];
__device__ float g_part [2*16*MM*LL];
__device__ float g_z0p  [8*BATCH*MM*DD];
// bf16 split buffers (all weights pre-split once per call)
__device__ __nv_bfloat16 g_ipwh[DD*KDIM];
__device__ __nv_bfloat16 g_ipwl[DD*KDIM];
__device__ __nv_bfloat16 g_w2hi[2*3712*KDIM];  // [dtw|Bw|Cw] x 2 layers
__device__ __nv_bfloat16 g_w2lo[2*3712*KDIM];
__device__ __nv_bfloat16 g_w1hi[7168*KDIM];    // [pkw|pvw]
__device__ __nv_bfloat16 g_w1lo[7168*KDIM];
__device__ __nv_bfloat16 g_ahi [BL*DD];
__device__ __nv_bfloat16 g_alo [BL*DD];

__device__ __forceinline__ __nv_bfloat16 bits_to_bf16(unsigned short s) {
    __nv_bfloat16_raw r; r.x = s; return __nv_bfloat16(r);
}

// ---------------- shared GEMM helpers ----------------
#define KC      64
#define NCHUNK  (KDIM/KC)    // 56
#define BPITCH  144
#define GTHR    512

__device__ __forceinline__ void cp16(uint32_t saddr, const void* g) {
    asm volatile("cp.async.cg.shared.global [%0], [%1], 16;" :: "r"(saddr), "l"(g));
}
__device__ __forceinline__ uint32_t smem_u32(const void* p) {
    uint32_t a;
    asm("{ .reg .u64 t; cvta.to.shared.u64 t, %1; cvt.u32.u64 %0, t; }"
        : "=r"(a) : "l"(p));
    return a;
}
__device__ __forceinline__ void mma_bf16(float* c, const uint32_t* a, const uint32_t* b) {
    asm volatile(
        "mma.sync.aligned.m16n8k16.row.col.f32.bf16.bf16.f32 "
        "{%0,%1,%2,%3}, {%4,%5,%6,%7}, {%8,%9}, {%0,%1,%2,%3};"
        : "+f"(c[0]), "+f"(c[1]), "+f"(c[2]), "+f"(c[3])
        : "r"(a[0]), "r"(a[1]), "r"(a[2]), "r"(a[3]), "r"(b[0]), "r"(b[1]));
}
#define LDSM_X4(r, addr) asm volatile( \
    "ldmatrix.sync.aligned.m8n8.x4.shared.b16 {%0,%1,%2,%3}, [%4];" \
    : "=r"((r)[0]), "=r"((r)[1]), "=r"((r)[2]), "=r"((r)[3]) : "r"(addr))

// =====================================================================
// bf16x3 GEMM, 128x128 tile (round-11 design)
// =====================================================================
#define TM      128
#define TILEB   (128*BPITCH)          // 18432
#define STG     (4*TILEB)             // 73728
#define SMEM_GEMM (3*STG)             // 221184

__device__ __forceinline__ void fill_stage(uint32_t sbase, int s,
        const __nv_bfloat16* __restrict__ Ah, const __nv_bfloat16* __restrict__ Al,
        const __nv_bfloat16* __restrict__ Wh, const __nv_bfloat16* __restrict__ Wl,
        int bm, int bn, int chunk, int tid) {
    uint32_t st = sbase + s * STG;
    const int k0 = chunk * KC;
    #pragma unroll
    for (int i = 0; i < 2; i++) {
        int idx = tid + i * GTHR, r = idx >> 3, j = idx & 7;
        uint32_t d = st + r * BPITCH + j * 16;
        size_t ga = (size_t)(bm + r) * KDIM + k0 + j * 8;
        size_t gw = (size_t)(bn + r) * KDIM + k0 + j * 8;
        cp16(d,             Ah + ga);
        cp16(d + TILEB,     Al + ga);
        cp16(d + 2 * TILEB, Wh + gw);
        cp16(d + 3 * TILEB, Wl + gw);
    }
}

// ACT: 0 = none, 1 = softplus (C1 tiles only)
template<int ACT>
__global__ void __launch_bounds__(GTHR, 1)
bf16_gemm(const __nv_bfloat16* __restrict__ Ah, const __nv_bfloat16* __restrict__ Al,
          const __nv_bfloat16* __restrict__ Wh, const __nv_bfloat16* __restrict__ Wl,
          const float* __restrict__ bias, float* __restrict__ C1,
          float* __restrict__ C2, int nsplitTiles, int c2s) {
    extern __shared__ char smc[];
    uint32_t sbase = smem_u32(smc);
    const int tid = threadIdx.x;
    const int wid = tid >> 5, lane = tid & 31;
    const int wm = wid >> 2, wn = wid & 3;
    const int g = lane >> 2, tg = lane & 3;
    const int bm = blockIdx.y * TM, bn = blockIdx.x * 128;

    const int q = lane >> 3, rr = lane & 7;
    const uint32_t offA = (uint32_t)((wm * 32 + rr + (q & 1) * 8) * BPITCH + (q >> 1) * 16);
    const uint32_t offB = (uint32_t)(2 * TILEB +
        (wn * 32 + (q >> 1) * 8 + rr) * BPITCH + (q & 1) * 16);

    float acc[2][4][4];
    #pragma unroll
    for (int i = 0; i < 2; i++)
        #pragma unroll
        for (int j = 0; j < 4; j++)
            #pragma unroll
            for (int k = 0; k < 4; k++) acc[i][j][k] = 0.f;

    fill_stage(sbase, 0, Ah, Al, Wh, Wl, bm, bn, 0, tid);
    asm volatile("cp.async.commit_group;" ::: "memory");
    fill_stage(sbase, 1, Ah, Al, Wh, Wl, bm, bn, 1, tid);
    asm volatile("cp.async.commit_group;" ::: "memory");

    int s = 0;
    for (int c = 0; c < NCHUNK; c++) {
        asm volatile("cp.async.wait_group 1;" ::: "memory");
        __syncthreads();
        int pn = c + 2;
        if (pn < NCHUNK) {
            int sp = s + 2; if (sp >= 3) sp -= 3;
            fill_stage(sbase, sp, Ah, Al, Wh, Wl, bm, bn, pn, tid);
        }
        asm volatile("cp.async.commit_group;" ::: "memory");

        const uint32_t base = sbase + s * STG;
        #pragma unroll
        for (int ks = 0; ks < 4; ks++) {
            const uint32_t kb = ks * 32;
            uint32_t ah[2][4], al[2][4], bh[4][2], bl[4][2];
            #pragma unroll
            for (int mi = 0; mi < 2; mi++) {
                uint32_t ad = base + offA + mi * (16 * BPITCH) + kb;
                LDSM_X4(ah[mi], ad);
                LDSM_X4(al[mi], ad + TILEB);
            }
            #pragma unroll
            for (int p = 0; p < 2; p++) {
                uint32_t bd = base + offB + p * (16 * BPITCH) + kb;
                LDSM_X4(&bh[2 * p][0], bd);
                LDSM_X4(&bl[2 * p][0], bd + TILEB);
            }
            #pragma unroll
            for (int mi = 0; mi < 2; mi++)
                #pragma unroll
                for (int nj = 0; nj < 4; nj++)
                    mma_bf16(acc[mi][nj], ah[mi], bh[nj]);
            #pragma unroll
            for (int mi = 0; mi < 2; mi++)
                #pragma unroll
                for (int nj = 0; nj < 4; nj++)
                    mma_bf16(acc[mi][nj], al[mi], bh[nj]);
            #pragma unroll
            for (int mi = 0; mi < 2; mi++)
                #pragma unroll
                for (int nj = 0; nj < 4; nj++)
                    mma_bf16(acc[mi][nj], ah[mi], bl[nj]);
        }
        s++; if (s >= 3) s = 0;
    }

    const bool first = ((int)blockIdx.x < nsplitTiles);
    float* Cb = first ? C1 : C2;
    const int colb = first ? bn : (bn - nsplitTiles * 128);
    const int strd = first ? DD : c2s;
    const bool ub = first && (bias != nullptr);
    #pragma unroll
    for (int mi = 0; mi < 2; mi++) {
        #pragma unroll
        for (int nj = 0; nj < 4; nj++) {
            int m = bm + wm * 32 + mi * 16 + g;
            int nl = colb + wn * 32 + nj * 8 + tg * 2;
            float v0 = acc[mi][nj][0], v1 = acc[mi][nj][1];
            float v2 = acc[mi][nj][2], v3 = acc[mi][nj][3];
            if (ub) {
                float b0 = bias[nl], b1 = bias[nl + 1];
                v0 += b0; v1 += b1; v2 += b0; v3 += b1;
            }
            if (ACT == 1 && first) {
                v0 = fmaxf(v0, 0.f) + log1pf(__expf(-fabsf(v0)));
                v1 = fmaxf(v1, 0.f) + log1pf(__expf(-fabsf(v1)));
                v2 = fmaxf(v2, 0.f) + log1pf(__expf(-fabsf(v2)));
                v3 = fmaxf(v3, 0.f) + log1pf(__expf(-fabsf(v3)));
            }
            *(float2*)&Cb[(size_t)m * strd + nl]       = make_float2(v0, v1);
            *(float2*)&Cb[(size_t)(m + 8) * strd + nl] = make_float2(v2, v3);
        }
    }
}

// ---------------- merged fp32 -> (hi, lo) bf16 split ----------------
__device__ __forceinline__ void split4(float4 f, uint2& hp, uint2& lp) {
    uint32_t u0 = __float_as_uint(f.x), u1 = __float_as_uint(f.y);
    uint32_t u2 = __float_as_uint(f.z), u3 = __float_as_uint(f.w);
    float h0 = __uint_as_float(u0 & 0xFFFF0000u);
    float h1 = __uint_as_float(u1 & 0xFFFF0000u);
    float h2 = __uint_as_float(u2 & 0xFFFF0000u);
    float h3 = __uint_as_float(u3 & 0xFFFF0000u);
    hp.x = __byte_perm(u0, u1, 0x7632);
    hp.y = __byte_perm(u2, u3, 0x7632);
    __nv_bfloat162 l0 = __floats2bfloat162_rn(f.x - h0, f.y - h1);
    __nv_bfloat162 l1 = __floats2bfloat162_rn(f.z - h2, f.w - h3);
    lp.x = *(uint32_t*)&l0;
    lp.y = *(uint32_t*)&l1;
}

#define N0Q (BL*DD/4)
#define N1Q (DD*KDIM/4)
#define N2Q (2*3712*KDIM/4)
#define N3Q (7168*KDIM/4)
#define NTQ (N0Q+N1Q+N2Q+N3Q)

__global__ void __launch_bounds__(256)
split_all(const float* __restrict__ tok, const float* __restrict__ ipw,
          const float* __restrict__ dtw, const float* __restrict__ Bw,
          const float* __restrict__ Cw, const float* __restrict__ pkw,
          const float* __restrict__ pvw,
          __nv_bfloat16* __restrict__ ah, __nv_bfloat16* __restrict__ al,
          __nv_bfloat16* __restrict__ iph, __nv_bfloat16* __restrict__ ipl,
          __nv_bfloat16* __restrict__ w2h, __nv_bfloat16* __restrict__ w2l,
          __nv_bfloat16* __restrict__ w1h, __nv_bfloat16* __restrict__ w1l) {
    long qd = (long)blockIdx.x * 256 + threadIdx.x;
    if (qd >= NTQ) return;
    const float* src;
    __nv_bfloat16 *dh, *dl;
    long e;
    if (qd < N0Q) {
        e = qd * 4; src = tok + e; dh = ah + e; dl = al + e;
    } else if (qd < N0Q + N1Q) {
        e = (qd - N0Q) * 4; src = ipw + e; dh = iph + e; dl = ipl + e;
    } else if (qd < N0Q + N1Q + N2Q) {
        e = (qd - N0Q - N1Q) * 4;
        int row = (int)(e / KDIM);
        int col = (int)(e - (long)row * KDIM);
        int layer = row / 3712, lr = row - layer * 3712;
        const float* s = (lr < 3584)
            ? dtw + (size_t)layer * DD * DD + (size_t)lr * KDIM
            : (lr < 3648)
            ? Bw + (size_t)layer * NST * DD + (size_t)(lr - 3584) * KDIM
            : Cw + (size_t)layer * NST * DD + (size_t)(lr - 3648) * KDIM;
        src = s + col; dh = w2h + e; dl = w2l + e;
    } else {
        e = (qd - N0Q - N1Q - N2Q) * 4;
        int row = (int)(e / KDIM);
        int col = (int)(e - (long)row * KDIM);
        const float* s = (row < 3584) ? pkw + (size_t)row * KDIM
                                      : pvw + (size_t)(row - 3584) * KDIM;
        src = s + col; dh = w1h + e; dl = w1l + e;
    }
    uint2 hp, lp;
    split4(*(const float4*)src, hp, lp);
    *(uint2*)dh = hp;
    *(uint2*)dl = lp;
}

// ---------------- reductions ----------------
__device__ __forceinline__ float blockReduceSum(float v, float* red) {
    int lane = threadIdx.x & 31, w = threadIdx.x >> 5;
    #pragma unroll
    for (int o = 16; o; o >>= 1) v += __shfl_xor_sync(0xffffffffu, v, o);
    if (lane == 0) red[w] = v;
    __syncthreads();
    float t = (threadIdx.x < 8) ? red[threadIdx.x] : 0.f;
    if (w == 0) {
        #pragma unroll
        for (int o = 4; o; o >>= 1) t += __shfl_xor_sync(0xffffffffu, t, o);
        if (lane == 0) red[0] = t;
    }
    __syncthreads();
    float r = red[0];
    __syncthreads();
    return r;
}
__device__ __forceinline__ float blockReduceMax(float v, float* red) {
    int lane = threadIdx.x & 31, w = threadIdx.x >> 5;
    #pragma unroll
    for (int o = 16; o; o >>= 1) v = fmaxf(v, __shfl_xor_sync(0xffffffffu, v, o));
    if (lane == 0) red[w] = v;
    __syncthreads();
    float t = (threadIdx.x < 8) ? red[threadIdx.x] : -3.4e38f;
    if (w == 0) {
        #pragma unroll
        for (int o = 4; o; o >>= 1) t = fmaxf(t, __shfl_xor_sync(0xffffffffu, t, o));
        if (lane == 0) red[0] = t;
    }
    __syncthreads();
    float r = red[0];
    __syncthreads();
    return r;
}

// ---------------- layernorm with fused bf16 split ----------------
__global__ void __launch_bounds__(256)
ln_split(const float* __restrict__ x, const float* __restrict__ g,
         const float* __restrict__ bta, float* __restrict__ out,
         __nv_bfloat16* __restrict__ hi, __nv_bfloat16* __restrict__ lo) {
    __shared__ float red[8];
    int row = blockIdx.x, tid = threadIdx.x;
    const float* xr = x + (size_t)row * DD;
    float v[14];
    float s = 0.f;
    #pragma unroll
    for (int i = 0; i < 14; i++) { v[i] = xr[tid + i * 256]; s += v[i]; }
    s = blockReduceSum(s, red);
    float mu = s * (1.f / DD);
    float q = 0.f;
    #pragma unroll
    for (int i = 0; i < 14; i++) { float d = v[i] - mu; q += d * d; }
    q = blockReduceSum(q, red);
    float rstd = rsqrtf(q * (1.f / DD) + 1e-5f);
    #pragma unroll
    for (int i = 0; i < 14; i++) {
        int c = tid + i * 256;
        float o = (v[i] - mu) * rstd * g[c] + bta[c];
        size_t off = (size_t)row * DD + c;
        out[off] = o;
        uint32_t u = __float_as_uint(o);
        float hf = __uint_as_float(u & 0xFFFF0000u);
        hi[off] = bits_to_bf16((unsigned short)(u >> 16));
        lo[off] = __float2bfloat16(o - hf);
    }
}

// ---------------- selective scan: 8 thr/channel, BC via smem ----------
#define SCD 16    // d-channels per block
#define SCH 8     // L-chunk
__global__ void __launch_bounds__(SCD*8)
scan_kernel(const float* __restrict__ xn, const float* __restrict__ dt,
            const float* __restrict__ BC, const float* __restrict__ Alog,
            const float* __restrict__ Dvec, float* __restrict__ x) {
    __shared__ float sBC[2][SCH][128];
    const int b   = blockIdx.y;
    const int tid = threadIdx.x;
    const int d   = blockIdx.x * SCD + (tid >> 3);
    const int ns  = tid & 7;
    float h[8], Aa[8];
    #pragma unroll
    for (int j = 0; j < 8; j++) {
        h[j]  = 0.f;
        Aa[j] = -__expf(Alog[(size_t)d * NST + ns * 8 + j]);
    }
    const float Dv = Dvec[d];
    const float* dtp = dt + (size_t)b * LL * DD + d;
    const float* xnp = xn + (size_t)b * LL * DD + d;
    float*       xp  = x  + (size_t)b * LL * DD + d;
    const float* BCrow = BC + (size_t)b * LL * 128;

    const uint32_t sb = smem_u32(sBC);
    for (int idx = tid; idx < SCH * 32; idx += SCD * 8) {
        int row = idx >> 5, qq = idx & 31;
        cp16(sb + (uint32_t)(row * 128 + qq * 4) * 4,
             BCrow + (size_t)row * 128 + qq * 4);
    }
    asm volatile("cp.async.commit_group;" ::: "memory");

    float dtv = dtp[0], xv = xnp[0], xo = xp[0];

    for (int ch = 0; ch < LL / SCH; ch++) {
        const int buf = ch & 1;
        if (ch + 1 < LL / SCH) {
            const int l0 = (ch + 1) * SCH;
            const uint32_t db = sb + (uint32_t)((buf ^ 1) * SCH * 128) * 4;
            for (int idx = tid; idx < SCH * 32; idx += SCD * 8) {
                int row = idx >> 5, qq = idx & 31;
                cp16(db + (uint32_t)(row * 128 + qq * 4) * 4,
                     BCrow + (size_t)(l0 + row) * 128 + qq * 4);
            }
        }
        asm volatile("cp.async.commit_group;" ::: "memory");
        asm volatile("cp.async.wait_group 1;" ::: "memory");
        __syncthreads();

        const float* sc = &sBC[buf][0][0];
        #pragma unroll
        for (int li = 0; li < SCH; li++) {
            const int l = ch * SCH + li;
            float dtn = 0.f, xnn = 0.f, xon = 0.f;
            if (l + 1 < LL) {
                size_t o = (size_t)(l + 1) * DD;
                dtn = dtp[o]; xnn = xnp[o]; xon = xp[o];
            }
            const float4* Bp = (const float4*)(sc + li * 128 + ns * 8);
            const float4* Cp = (const float4*)(sc + li * 128 + 64 + ns * 8);
            float t = dtv * xv;
            float y = 0.f;
            #pragma unroll
            for (int qq = 0; qq < 2; qq++) {
                float4 Bv = Bp[qq];
                float4 Cv = Cp[qq];
                float* hq = h + qq * 4;
                const float* Aq = Aa + qq * 4;
                hq[0] = fmaf(__expf(dtv * Aq[0]), hq[0], Bv.x * t);
                hq[1] = fmaf(__expf(dtv * Aq[1]), hq[1], Bv.y * t);
                hq[2] = fmaf(__expf(dtv * Aq[2]), hq[2], Bv.z * t);
                hq[3] = fmaf(__expf(dtv * Aq[3]), hq[3], Bv.w * t);
                y += Cv.x * hq[0] + Cv.y * hq[1] + Cv.z * hq[2] + Cv.w * hq[3];
            }
            y += __shfl_xor_sync(0xffffffffu, y, 1);
            y += __shfl_xor_sync(0xffffffffu, y, 2);
            y += __shfl_xor_sync(0xffffffffu, y, 4);
            if (ns == 0) xp[(size_t)l * DD] = fmaf(Dv, xo, y);
            dtv = dtn; xv = xnn; xo = xon;
        }
        __syncthreads();
    }
}

// ---------------- attention scores: split-K, both batches ----------------
__global__ void __launch_bounds__(128)
attn_scores(const float* __restrict__ A, const float* __restrict__ keys,
            float* __restrict__ part) {
    __shared__ float As[16][64];
    __shared__ float Ws[16][128];
    const int tid = threadIdx.x;
    const int bn = blockIdx.x * 128;
    const int bat = blockIdx.y;
    const int kbase = blockIdx.z * (KDIM / 16);
    const float* W = keys + (size_t)bat * LL * KDIM;
    const int lr = tid >> 2;
    const int lk = (tid & 3) << 2;
    const int tx = tid & 15;
    const int ty = tid >> 4;
    float acc[8][8];
    #pragma unroll
    for (int i = 0; i < 8; i++)
        #pragma unroll
        for (int j = 0; j < 8; j++) acc[i][j] = 0.f;

    for (int k0 = kbase; k0 < kbase + KDIM / 16; k0 += 16) {
        {
            int r = lr;
            float4 v = *(const float4*)(A + (size_t)r * KDIM + k0 + lk);
            As[lk + 0][r] = v.x; As[lk + 1][r] = v.y;
            As[lk + 2][r] = v.z; As[lk + 3][r] = v.w;
            r = lr + 32;
            v = *(const float4*)(A + (size_t)r * KDIM + k0 + lk);
            As[lk + 0][r] = v.x; As[lk + 1][r] = v.y;
            As[lk + 2][r] = v.z; As[lk + 3][r] = v.w;
        }
        #pragma unroll
        for (int hh = 0; hh < 4; hh++) {
            int r = lr + hh * 32;
            float4 v = *(const float4*)(W + (size_t)(bn + r) * KDIM + k0 + lk);
            Ws[lk + 0][r] = v.x; Ws[lk + 1][r] = v.y;
            Ws[lk + 2][r] = v.z; Ws[lk + 3][r] = v.w;
        }
        __syncthreads();
        #pragma unroll
        for (int kk = 0; kk < 16; kk++) {
            float a[8], w[8];
            *(float4*)(a)     = *(const float4*)&As[kk][ty * 8];
            *(float4*)(a + 4) = *(const float4*)&As[kk][ty * 8 + 4];
            *(float4*)(w)     = *(const float4*)&Ws[kk][tx * 8];
            *(float4*)(w + 4) = *(const float4*)&Ws[kk][tx * 8 + 4];
            #pragma unroll
            for (int i = 0; i < 8; i++)
                #pragma unroll
                for (int j = 0; j < 8; j++)
                    acc[i][j] = fmaf(a[i], w[j], acc[i][j]);
        }
        __syncthreads();
    }
    float* outp = part + (size_t)bat * 16 * MM * LL + (size_t)blockIdx.z * MM * LL;
    #pragma unroll
    for (int i = 0; i < 8; i++) {
        int row = ty * 8 + i;
        #pragma unroll
        for (int j4 = 0; j4 < 2; j4++) {
            float4 o = make_float4(acc[i][j4*4+0], acc[i][j4*4+1],
                                   acc[i][j4*4+2], acc[i][j4*4+3]);
            *(float4*)&outp[(size_t)row * LL + bn + tx * 8 + j4 * 4] = o;
        }
    }
}

// fused: sum 16 split-K partials, scale, softmax over 256 cols
__global__ void __launch_bounds__(256)
attn_softmax(const float* __restrict__ part, float* __restrict__ scores,
             float scal) {
    __shared__ float red[8];
    int bx = blockIdx.x;
    int b = bx >> 6, m = bx & 63;
    int l = threadIdx.x;
    const float* p = part + (size_t)b * 16 * MM * LL + (size_t)m * LL + l;
    float s = 0.f;
    #pragma unroll
    for (int z = 0; z < 16; z++) s += p[(size_t)z * MM * LL];
    float v = s * scal;
    float mx = blockReduceMax(v, red);
    float e = __expf(v - mx);
    float sum = blockReduceSum(e, red);
    scores[(size_t)bx * LL + l] = e / sum;
}

// ---------------- mean over L ----------------
__global__ void meanL(const float* __restrict__ xo, float* __restrict__ mean) {
    int idx = blockIdx.x * 256 + threadIdx.x;
    int b = idx / DD, d = idx % DD;
    float s = 0.f;
    for (int l = 0; l < LL; l++) s += xo[(size_t)(b * LL + l) * DD + d];
    mean[idx] = s * (1.f / LL);
}

// ---------------- warp-per-output dot (cond path) ----------
template<int ACT>
__global__ void rowdot(const float* __restrict__ A, const float* __restrict__ W,
                       const float* __restrict__ bias, float* __restrict__ out,
                       int rows, int cols, int K) {
    int gw = (blockIdx.x * blockDim.x + threadIdx.x) >> 5;
    int lane = threadIdx.x & 31;
    if (gw >= rows * cols) return;
    int r = gw / cols, c = gw % cols;
    const float4* a = (const float4*)(A + (size_t)r * K);
    const float4* w = (const float4*)(W + (size_t)c * K);
    int K4 = K >> 2;
    float s = 0.f;
    for (int k = lane; k < K4; k += 32) {
        float4 x = a[k], y = w[k];
        s += x.x * y.x + x.y * y.y + x.z * y.z + x.w * y.w;
    }
    #pragma unroll
    for (int o = 16; o; o >>= 1) s += __shfl_xor_sync(0xffffffffu, s, o);
    if (lane == 0) {
        s += bias[c];
        if (ACT == 2) s = s / (1.f + __expf(-s));
        out[(size_t)r * cols + c] = s;
    }
}

// ---------------- z0 = attn @ values ----------------
__global__ void __launch_bounds__(256)
z0_partial(const float* __restrict__ attn, const float* __restrict__ vals,
           float* __restrict__ part) {
    int d  = blockIdx.x * 256 + threadIdx.x;
    int b  = blockIdx.y;
    int sp = blockIdx.z;
    __shared__ float sa[64][32];
    int l0 = sp * 32;
    for (int i = threadIdx.x; i < 2048; i += 256) {
        int m = i >> 5, li = i & 31;
        sa[m][li] = attn[(size_t)(b * MM + m) * LL + l0 + li];
    }
    __syncthreads();
    float acc[64];
    #pragma unroll
    for (int m = 0; m < 64; m++) acc[m] = 0.f;
    for (int li = 0; li < 32; li += 4) {
        float v0 = vals[(size_t)(b * LL + l0 + li + 0) * DD + d];
        float v1 = vals[(size_t)(b * LL + l0 + li + 1) * DD + d];
        float v2 = vals[(size_t)(b * LL + l0 + li + 2) * DD + d];
        float v3 = vals[(size_t)(b * LL + l0 + li + 3) * DD + d];
        #pragma unroll
        for (int m = 0; m < 64; m++) {
            float4 a4 = *(const float4*)&sa[m][li];
            acc[m] = fmaf(a4.x, v0, fmaf(a4.y, v1, fmaf(a4.z, v2, fmaf(a4.w, v3, acc[m]))));
        }
    }
    #pragma unroll
    for (int m = 0; m < 64; m++)
        part[((size_t)(sp * BATCH + b) * MM + m) * DD + d] = acc[m];
}

__global__ void z0_reduce(const float* __restrict__ part, float* __restrict__ out) {
    int i = blockIdx.x * 256 + threadIdx.x;
    float s = 0.f;
    #pragma unroll
    for (int z = 0; z < 8; z++) s += part[(size_t)z * (BATCH * MM * DD) + i];
    out[i] = s;
}

// ---------------- host side ----------------
extern "C" void kernel_launch(void* const* d_in, const int* in_sizes, int n_in,
                              void* d_out, int out_size) {
    const float* tok  = (const float*)d_in[0];
    const float* ipw  = (const float*)d_in[1];
    const float* ipb  = (const float*)d_in[2];
    const float* ng   = (const float*)d_in[3];
    const float* nb   = (const float*)d_in[4];
    const float* dtw  = (const float*)d_in[5];
    const float* dtb  = (const float*)d_in[6];
    const float* Bw   = (const float*)d_in[7];
    const float* Cw   = (const float*)d_in[8];
    const float* Dvv  = (const float*)d_in[9];
    const float* Alog = (const float*)d_in[10];
    const float* og   = (const float*)d_in[11];
    const float* ob   = (const float*)d_in[12];
    const float* lq   = (const float*)d_in[13];
    const float* pkw  = (const float*)d_in[14];
    const float* pvw  = (const float*)d_in[15];
    const float* w1   = (const float*)d_in[16];
    const float* b1   = (const float*)d_in[17];
    const float* w2   = (const float*)d_in[18];
    const float* b2   = (const float*)d_in[19];
    float* out = (float*)d_out;

    float *px, *pxn, *pdt, *pkeys, *pvals, *pxo, *pBC, *pmean, *pc1, *pscores, *ppart, *pz0p;
    __nv_bfloat16 *piph, *pipl, *pw2h, *pw2l, *pw1h, *pw1l, *pah, *pal;
    cudaGetSymbolAddress((void**)&px,     g_x);
    cudaGetSymbolAddress((void**)&pxn,    g_xn);
    cudaGetSymbolAddress((void**)&pdt,    g_dt);
    cudaGetSymbolAddress((void**)&pkeys,  g_keys);
    cudaGetSymbolAddress((void**)&pvals,  g_vals);
    cudaGetSymbolAddress((void**)&pxo,    g_xo);
    cudaGetSymbolAddress((void**)&pBC,    g_BC);
    cudaGetSymbolAddress((void**)&pmean,  g_mean);
    cudaGetSymbolAddress((void**)&pc1,    g_c1);
    cudaGetSymbolAddress((void**)&pscores,g_scores);
    cudaGetSymbolAddress((void**)&ppart,  g_part);
    cudaGetSymbolAddress((void**)&pz0p,   g_z0p);
    cudaGetSymbolAddress((void**)&piph,   g_ipwh);
    cudaGetSymbolAddress((void**)&pipl,   g_ipwl);
    cudaGetSymbolAddress((void**)&pw2h,   g_w2hi);
    cudaGetSymbolAddress((void**)&pw2l,   g_w2lo);
    cudaGetSymbolAddress((void**)&pw1h,   g_w1hi);
    cudaGetSymbolAddress((void**)&pw1l,   g_w1lo);
    cudaGetSymbolAddress((void**)&pah,    g_ahi);
    cudaGetSymbolAddress((void**)&pal,    g_alo);

    cudaFuncSetAttribute(bf16_gemm<0>, cudaFuncAttributeMaxDynamicSharedMemorySize, SMEM_GEMM);
    cudaFuncSetAttribute(bf16_gemm<1>, cudaFuncAttributeMaxDynamicSharedMemorySize, SMEM_GEMM);

    // one merged split for ALL weights + token activations
    split_all<<<(int)((NTQ + 255) / 256), 256>>>(tok, ipw, dtw, Bw, Cw, pkw, pvw,
                                                 pah, pal, piph, pipl,
                                                 pw2h, pw2l, pw1h, pw1l);
    // input projection
    bf16_gemm<0><<<dim3(28, 4), GTHR, SMEM_GEMM>>>(pah, pal, piph, pipl,
                                                   ipb, px, nullptr, 28, 0);
    // layer 0
    ln_split<<<BL, 256>>>(px, ng, nb, pxn, pah, pal);
    bf16_gemm<1><<<dim3(29, 4), GTHR, SMEM_GEMM>>>(pah, pal, pw2h, pw2l,
                                                   dtb, pdt, pBC, 28, 128);
    scan_kernel<<<dim3(DD / SCD, BATCH), SCD * 8>>>(pxn, pdt, pBC, Alog, Dvv, px);
    // layer 1
    ln_split<<<BL, 256>>>(px, ng + DD, nb + DD, pxn, pah, pal);
    bf16_gemm<1><<<dim3(29, 4), GTHR, SMEM_GEMM>>>(pah, pal,
                                                   pw2h + (size_t)3712 * KDIM,
                                                   pw2l + (size_t)3712 * KDIM,
                                                   dtb + DD, pdt, pBC, 28, 128);
    scan_kernel<<<dim3(DD / SCD, BATCH), SCD * 8>>>(pxn, pdt, pBC,
                                                    Alog + (size_t)DD * NST,
                                                    Dvv + DD, px);
    // output norm (+ split for pooling GEMM)
    ln_split<<<BL, 256>>>(px, og, ob, pxo, pah, pal);

    // conditioning head
    meanL<<<(BATCH * DD) / 256, 256>>>(pxo, pmean);
    rowdot<2><<<(BATCH * CONDD * 32 + 255) / 256, 256>>>(pmean, w1, b1, pc1, BATCH, CONDD, DD);
    rowdot<0><<<(BATCH * CONDD * 32 + 255) / 256, 256>>>(pc1, w2, b2, out + BATCH * MM * DD,
                                                         BATCH, CONDD, CONDD);

    // fused pool_k | pool_v projection (N = 7168), 128x128 tiles
    bf16_gemm<0><<<dim3(56, 4), GTHR, SMEM_GEMM>>>(pah, pal, pw1h, pw1l,
                                                   nullptr, pkeys, pvals, 28, DD);

    // attention: one launch covering both batches, then fused reduce+softmax
    attn_scores<<<dim3(LL / 128, BATCH, 16), 128>>>(lq, pkeys, ppart);
    attn_softmax<<<BATCH * MM, 256>>>(ppart, pscores, 1.f / sqrtf((float)DD));

    // z0 = attn @ values
    z0_partial<<<dim3(DD / 256, BATCH, 8), 256>>>(pscores, pvals, pz0p);
    z0_reduce<<<(BATCH * MM * DD) / 256, 256>>>(pz0p, out);
}

// round 17
// speedup vs baseline: 1.0226x; 1.0205x over previous
#include <cuda_runtime.h>
#include <cuda_bf16.h>
#include <math.h>
#include <stdint.h>

// ---------------- problem constants ----------------
#define DD     3584
#define BATCH  2
#define LL     256
#define BL     512      // BATCH*LL
#define NST    64       // ssm state dim
#define MM     64       // latent vectors
#define CONDD  256
#define KDIM   3584

// ---------------- scratch (device globals; no allocation) ----------------
__device__ float g_x    [BL*DD];
__device__ float g_xn   [BL*DD];
__device__ float g_dt   [BL*DD];
__device__ float g_keys [BL*DD];
__device__ float g_vals [BL*DD];
__device__ float g_xo   [BL*DD];
__device__ float g_BC   [BL*128];
__device__ float g_mean [BATCH*DD];
__device__ float g_c1   [BATCH*CONDD];
__device__ float g_scores[BATCH*MM*LL];
__device__ float g_part [2*16*MM*LL];
__device__ float g_z0p  [8*BATCH*MM*DD];
// bf16 split buffers (all weights pre-split once per call)
__device__ __nv_bfloat16 g_ipwh[DD*KDIM];
__device__ __nv_bfloat16 g_ipwl[DD*KDIM];
__device__ __nv_bfloat16 g_w2hi[2*3712*KDIM];  // [dtw|Bw|Cw] x 2 layers
__device__ __nv_bfloat16 g_w2lo[2*3712*KDIM];
__device__ __nv_bfloat16 g_w1hi[7168*KDIM];    // [pkw|pvw]
__device__ __nv_bfloat16 g_w1lo[7168*KDIM];
__device__ __nv_bfloat16 g_ahi [BL*DD];
__device__ __nv_bfloat16 g_alo [BL*DD];

__device__ __forceinline__ __nv_bfloat16 bits_to_bf16(unsigned short s) {
    __nv_bfloat16_raw r; r.x = s; return __nv_bfloat16(r);
}

// ---------------- shared GEMM helpers ----------------
#define KC      64
#define NCHUNK  (KDIM/KC)    // 56
#define BPITCH  144
#define GTHR    512

__device__ __forceinline__ void cp16(uint32_t saddr, const void* g) {
    asm volatile("cp.async.cg.shared.global [%0], [%1], 16;" :: "r"(saddr), "l"(g));
}
__device__ __forceinline__ uint32_t smem_u32(const void* p) {
    uint32_t a;
    asm("{ .reg .u64 t; cvta.to.shared.u64 t, %1; cvt.u32.u64 %0, t; }"
        : "=r"(a) : "l"(p));
    return a;
}
__device__ __forceinline__ void mma_bf16(float* c, const uint32_t* a, const uint32_t* b) {
    asm volatile(
        "mma.sync.aligned.m16n8k16.row.col.f32.bf16.bf16.f32 "
        "{%0,%1,%2,%3}, {%4,%5,%6,%7}, {%8,%9}, {%0,%1,%2,%3};"
        : "+f"(c[0]), "+f"(c[1]), "+f"(c[2]), "+f"(c[3])
        : "r"(a[0]), "r"(a[1]), "r"(a[2]), "r"(a[3]), "r"(b[0]), "r"(b[1]));
}
#define LDSM_X4(r, addr) asm volatile( \
    "ldmatrix.sync.aligned.m8n8.x4.shared.b16 {%0,%1,%2,%3}, [%4];" \
    : "=r"((r)[0]), "=r"((r)[1]), "=r"((r)[2]), "=r"((r)[3]) : "r"(addr))

// =====================================================================
// bf16x3 GEMM, 128x128 tile (round-11 design)
// =====================================================================
#define TM      128
#define TILEB   (128*BPITCH)          // 18432
#define STG     (4*TILEB)             // 73728
#define SMEM_GEMM (3*STG)             // 221184

__device__ __forceinline__ void fill_stage(uint32_t sbase, int s,
        const __nv_bfloat16* __restrict__ Ah, const __nv_bfloat16* __restrict__ Al,
        const __nv_bfloat16* __restrict__ Wh, const __nv_bfloat16* __restrict__ Wl,
        int bm, int bn, int chunk, int tid) {
    uint32_t st = sbase + s * STG;
    const int k0 = chunk * KC;
    #pragma unroll
    for (int i = 0; i < 2; i++) {
        int idx = tid + i * GTHR, r = idx >> 3, j = idx & 7;
        uint32_t d = st + r * BPITCH + j * 16;
        size_t ga = (size_t)(bm + r) * KDIM + k0 + j * 8;
        size_t gw = (size_t)(bn + r) * KDIM + k0 + j * 8;
        cp16(d,             Ah + ga);
        cp16(d + TILEB,     Al + ga);
        cp16(d + 2 * TILEB, Wh + gw);
        cp16(d + 3 * TILEB, Wl + gw);
    }
}

// ACT: 0 = none, 1 = softplus (C1 tiles only)
template<int ACT>
__global__ void __launch_bounds__(GTHR, 1)
bf16_gemm(const __nv_bfloat16* __restrict__ Ah, const __nv_bfloat16* __restrict__ Al,
          const __nv_bfloat16* __restrict__ Wh, const __nv_bfloat16* __restrict__ Wl,
          const float* __restrict__ bias, float* __restrict__ C1,
          float* __restrict__ C2, int nsplitTiles, int c2s) {
    extern __shared__ char smc[];
    uint32_t sbase = smem_u32(smc);
    const int tid = threadIdx.x;
    const int wid = tid >> 5, lane = tid & 31;
    const int wm = wid >> 2, wn = wid & 3;
    const int g = lane >> 2, tg = lane & 3;
    const int bm = blockIdx.y * TM, bn = blockIdx.x * 128;

    const int q = lane >> 3, rr = lane & 7;
    const uint32_t offA = (uint32_t)((wm * 32 + rr + (q & 1) * 8) * BPITCH + (q >> 1) * 16);
    const uint32_t offB = (uint32_t)(2 * TILEB +
        (wn * 32 + (q >> 1) * 8 + rr) * BPITCH + (q & 1) * 16);

    float acc[2][4][4];
    #pragma unroll
    for (int i = 0; i < 2; i++)
        #pragma unroll
        for (int j = 0; j < 4; j++)
            #pragma unroll
            for (int k = 0; k < 4; k++) acc[i][j][k] = 0.f;

    fill_stage(sbase, 0, Ah, Al, Wh, Wl, bm, bn, 0, tid);
    asm volatile("cp.async.commit_group;" ::: "memory");
    fill_stage(sbase, 1, Ah, Al, Wh, Wl, bm, bn, 1, tid);
    asm volatile("cp.async.commit_group;" ::: "memory");

    int s = 0;
    for (int c = 0; c < NCHUNK; c++) {
        asm volatile("cp.async.wait_group 1;" ::: "memory");
        __syncthreads();
        int pn = c + 2;
        if (pn < NCHUNK) {
            int sp = s + 2; if (sp >= 3) sp -= 3;
            fill_stage(sbase, sp, Ah, Al, Wh, Wl, bm, bn, pn, tid);
        }
        asm volatile("cp.async.commit_group;" ::: "memory");

        const uint32_t base = sbase + s * STG;
        #pragma unroll
        for (int ks = 0; ks < 4; ks++) {
            const uint32_t kb = ks * 32;
            uint32_t ah[2][4], al[2][4], bh[4][2], bl[4][2];
            #pragma unroll
            for (int mi = 0; mi < 2; mi++) {
                uint32_t ad = base + offA + mi * (16 * BPITCH) + kb;
                LDSM_X4(ah[mi], ad);
                LDSM_X4(al[mi], ad + TILEB);
            }
            #pragma unroll
            for (int p = 0; p < 2; p++) {
                uint32_t bd = base + offB + p * (16 * BPITCH) + kb;
                LDSM_X4(&bh[2 * p][0], bd);
                LDSM_X4(&bl[2 * p][0], bd + TILEB);
            }
            #pragma unroll
            for (int mi = 0; mi < 2; mi++)
                #pragma unroll
                for (int nj = 0; nj < 4; nj++)
                    mma_bf16(acc[mi][nj], ah[mi], bh[nj]);
            #pragma unroll
            for (int mi = 0; mi < 2; mi++)
                #pragma unroll
                for (int nj = 0; nj < 4; nj++)
                    mma_bf16(acc[mi][nj], al[mi], bh[nj]);
            #pragma unroll
            for (int mi = 0; mi < 2; mi++)
                #pragma unroll
                for (int nj = 0; nj < 4; nj++)
                    mma_bf16(acc[mi][nj], ah[mi], bl[nj]);
        }
        s++; if (s >= 3) s = 0;
    }

    const bool first = ((int)blockIdx.x < nsplitTiles);
    float* Cb = first ? C1 : C2;
    const int colb = first ? bn : (bn - nsplitTiles * 128);
    const int strd = first ? DD : c2s;
    const bool ub = first && (bias != nullptr);
    #pragma unroll
    for (int mi = 0; mi < 2; mi++) {
        #pragma unroll
        for (int nj = 0; nj < 4; nj++) {
            int m = bm + wm * 32 + mi * 16 + g;
            int nl = colb + wn * 32 + nj * 8 + tg * 2;
            float v0 = acc[mi][nj][0], v1 = acc[mi][nj][1];
            float v2 = acc[mi][nj][2], v3 = acc[mi][nj][3];
            if (ub) {
                float b0 = bias[nl], b1 = bias[nl + 1];
                v0 += b0; v1 += b1; v2 += b0; v3 += b1;
            }
            if (ACT == 1 && first) {
                v0 = fmaxf(v0, 0.f) + log1pf(__expf(-fabsf(v0)));
                v1 = fmaxf(v1, 0.f) + log1pf(__expf(-fabsf(v1)));
                v2 = fmaxf(v2, 0.f) + log1pf(__expf(-fabsf(v2)));
                v3 = fmaxf(v3, 0.f) + log1pf(__expf(-fabsf(v3)));
            }
            *(float2*)&Cb[(size_t)m * strd + nl]       = make_float2(v0, v1);
            *(float2*)&Cb[(size_t)(m + 8) * strd + nl] = make_float2(v2, v3);
        }
    }
}

// ---------------- fp32 -> (hi, lo) bf16 split ----------------
__device__ __forceinline__ void split4(float4 f, uint2& hp, uint2& lp) {
    uint32_t u0 = __float_as_uint(f.x), u1 = __float_as_uint(f.y);
    uint32_t u2 = __float_as_uint(f.z), u3 = __float_as_uint(f.w);
    float h0 = __uint_as_float(u0 & 0xFFFF0000u);
    float h1 = __uint_as_float(u1 & 0xFFFF0000u);
    float h2 = __uint_as_float(u2 & 0xFFFF0000u);
    float h3 = __uint_as_float(u3 & 0xFFFF0000u);
    hp.x = __byte_perm(u0, u1, 0x7632);
    hp.y = __byte_perm(u2, u3, 0x7632);
    __nv_bfloat162 l0 = __floats2bfloat162_rn(f.x - h0, f.y - h1);
    __nv_bfloat162 l1 = __floats2bfloat162_rn(f.z - h2, f.w - h3);
    lp.x = *(uint32_t*)&l0;
    lp.y = *(uint32_t*)&l1;
}

#define N0Q (BL*DD/4)              // tok
#define N1Q (DD*KDIM/4)            // ipw
#define NIPQ (N0Q+N1Q)
#define N2Q (2*3712*KDIM/4)        // dt|B|C x2
#define N3Q (7168*KDIM/4)          // pk|pv
#define NRQ (N2Q+N3Q)

// split tok + ipw (needed before ip GEMM)
__global__ void __launch_bounds__(256)
split_ip(const float* __restrict__ tok, const float* __restrict__ ipw,
         __nv_bfloat16* __restrict__ ah, __nv_bfloat16* __restrict__ al,
         __nv_bfloat16* __restrict__ iph, __nv_bfloat16* __restrict__ ipl) {
    long qd = (long)blockIdx.x * 256 + threadIdx.x;
    if (qd >= NIPQ) return;
    const float* src;
    __nv_bfloat16 *dh, *dl;
    long e;
    if (qd < N0Q) {
        e = qd * 4; src = tok + e; dh = ah + e; dl = al + e;
    } else {
        e = (qd - N0Q) * 4; src = ipw + e; dh = iph + e; dl = ipl + e;
    }
    uint2 hp, lp;
    split4(*(const float4*)src, hp, lp);
    *(uint2*)dh = hp;
    *(uint2*)dl = lp;
}

// split dt|B|C (both layers) + pk|pv  (runs concurrently with ip GEMM)
__global__ void __launch_bounds__(256)
split_rest(const float* __restrict__ dtw, const float* __restrict__ Bw,
           const float* __restrict__ Cw, const float* __restrict__ pkw,
           const float* __restrict__ pvw,
           __nv_bfloat16* __restrict__ w2h, __nv_bfloat16* __restrict__ w2l,
           __nv_bfloat16* __restrict__ w1h, __nv_bfloat16* __restrict__ w1l) {
    long qd = (long)blockIdx.x * 256 + threadIdx.x;
    if (qd >= NRQ) return;
    const float* src;
    __nv_bfloat16 *dh, *dl;
    long e;
    if (qd < N2Q) {
        e = qd * 4;
        int row = (int)(e / KDIM);
        int col = (int)(e - (long)row * KDIM);
        int layer = row / 3712, lr = row - layer * 3712;
        const float* s = (lr < 3584)
            ? dtw + (size_t)layer * DD * DD + (size_t)lr * KDIM
            : (lr < 3648)
            ? Bw + (size_t)layer * NST * DD + (size_t)(lr - 3584) * KDIM
            : Cw + (size_t)layer * NST * DD + (size_t)(lr - 3648) * KDIM;
        src = s + col; dh = w2h + e; dl = w2l + e;
    } else {
        e = (qd - N2Q) * 4;
        int row = (int)(e / KDIM);
        int col = (int)(e - (long)row * KDIM);
        const float* s = (row < 3584) ? pkw + (size_t)row * KDIM
                                      : pvw + (size_t)(row - 3584) * KDIM;
        src = s + col; dh = w1h + e; dl = w1l + e;
    }
    uint2 hp, lp;
    split4(*(const float4*)src, hp, lp);
    *(uint2*)dh = hp;
    *(uint2*)dl = lp;
}

// ---------------- reductions ----------------
__device__ __forceinline__ float blockReduceSum(float v, float* red) {
    int lane = threadIdx.x & 31, w = threadIdx.x >> 5;
    #pragma unroll
    for (int o = 16; o; o >>= 1) v += __shfl_xor_sync(0xffffffffu, v, o);
    if (lane == 0) red[w] = v;
    __syncthreads();
    float t = (threadIdx.x < 8) ? red[threadIdx.x] : 0.f;
    if (w == 0) {
        #pragma unroll
        for (int o = 4; o; o >>= 1) t += __shfl_xor_sync(0xffffffffu, t, o);
        if (lane == 0) red[0] = t;
    }
    __syncthreads();
    float r = red[0];
    __syncthreads();
    return r;
}
__device__ __forceinline__ float blockReduceMax(float v, float* red) {
    int lane = threadIdx.x & 31, w = threadIdx.x >> 5;
    #pragma unroll
    for (int o = 16; o; o >>= 1) v = fmaxf(v, __shfl_xor_sync(0xffffffffu, v, o));
    if (lane == 0) red[w] = v;
    __syncthreads();
    float t = (threadIdx.x < 8) ? red[threadIdx.x] : -3.4e38f;
    if (w == 0) {
        #pragma unroll
        for (int o = 4; o; o >>= 1) t = fmaxf(t, __shfl_xor_sync(0xffffffffu, t, o));
        if (lane == 0) red[0] = t;
    }
    __syncthreads();
    float r = red[0];
    __syncthreads();
    return r;
}

// ---------------- layernorm with fused bf16 split ----------------
__global__ void __launch_bounds__(256)
ln_split(const float* __restrict__ x, const float* __restrict__ g,
         const float* __restrict__ bta, float* __restrict__ out,
         __nv_bfloat16* __restrict__ hi, __nv_bfloat16* __restrict__ lo) {
    __shared__ float red[8];
    int row = blockIdx.x, tid = threadIdx.x;
    const float* xr = x + (size_t)row * DD;
    float v[14];
    float s = 0.f;
    #pragma unroll
    for (int i = 0; i < 14; i++) { v[i] = xr[tid + i * 256]; s += v[i]; }
    s = blockReduceSum(s, red);
    float mu = s * (1.f / DD);
    float q = 0.f;
    #pragma unroll
    for (int i = 0; i < 14; i++) { float d = v[i] - mu; q += d * d; }
    q = blockReduceSum(q, red);
    float rstd = rsqrtf(q * (1.f / DD) + 1e-5f);
    #pragma unroll
    for (int i = 0; i < 14; i++) {
        int c = tid + i * 256;
        float o = (v[i] - mu) * rstd * g[c] + bta[c];
        size_t off = (size_t)row * DD + c;
        out[off] = o;
        uint32_t u = __float_as_uint(o);
        float hf = __uint_as_float(u & 0xFFFF0000u);
        hi[off] = bits_to_bf16((unsigned short)(u >> 16));
        lo[off] = __float2bfloat16(o - hf);
    }
}

// ---------------- selective scan: 8 thr/channel, BC via smem ----------
#define SCD 16    // d-channels per block
#define SCH 8     // L-chunk
__global__ void __launch_bounds__(SCD*8)
scan_kernel(const float* __restrict__ xn, const float* __restrict__ dt,
            const float* __restrict__ BC, const float* __restrict__ Alog,
            const float* __restrict__ Dvec, float* __restrict__ x) {
    __shared__ float sBC[2][SCH][128];
    const int b   = blockIdx.y;
    const int tid = threadIdx.x;
    const int d   = blockIdx.x * SCD + (tid >> 3);
    const int ns  = tid & 7;
    float h[8], Aa[8];
    #pragma unroll
    for (int j = 0; j < 8; j++) {
        h[j]  = 0.f;
        Aa[j] = -__expf(Alog[(size_t)d * NST + ns * 8 + j]);
    }
    const float Dv = Dvec[d];
    const float* dtp = dt + (size_t)b * LL * DD + d;
    const float* xnp = xn + (size_t)b * LL * DD + d;
    float*       xp  = x  + (size_t)b * LL * DD + d;
    const float* BCrow = BC + (size_t)b * LL * 128;

    const uint32_t sb = smem_u32(sBC);
    for (int idx = tid; idx < SCH * 32; idx += SCD * 8) {
        int row = idx >> 5, qq = idx & 31;
        cp16(sb + (uint32_t)(row * 128 + qq * 4) * 4,
             BCrow + (size_t)row * 128 + qq * 4);
    }
    asm volatile("cp.async.commit_group;" ::: "memory");

    float dtv = dtp[0], xv = xnp[0], xo = xp[0];

    for (int ch = 0; ch < LL / SCH; ch++) {
        const int buf = ch & 1;
        if (ch + 1 < LL / SCH) {
            const int l0 = (ch + 1) * SCH;
            const uint32_t db = sb + (uint32_t)((buf ^ 1) * SCH * 128) * 4;
            for (int idx = tid; idx < SCH * 32; idx += SCD * 8) {
                int row = idx >> 5, qq = idx & 31;
                cp16(db + (uint32_t)(row * 128 + qq * 4) * 4,
                     BCrow + (size_t)(l0 + row) * 128 + qq * 4);
            }
        }
        asm volatile("cp.async.commit_group;" ::: "memory");
        asm volatile("cp.async.wait_group 1;" ::: "memory");
        __syncthreads();

        const float* sc = &sBC[buf][0][0];
        #pragma unroll
        for (int li = 0; li < SCH; li++) {
            const int l = ch * SCH + li;
            float dtn = 0.f, xnn = 0.f, xon = 0.f;
            if (l + 1 < LL) {
                size_t o = (size_t)(l + 1) * DD;
                dtn = dtp[o]; xnn = xnp[o]; xon = xp[o];
            }
            const float4* Bp = (const float4*)(sc + li * 128 + ns * 8);
            const float4* Cp = (const float4*)(sc + li * 128 + 64 + ns * 8);
            float t = dtv * xv;
            float y = 0.f;
            #pragma unroll
            for (int qq = 0; qq < 2; qq++) {
                float4 Bv = Bp[qq];
                float4 Cv = Cp[qq];
                float* hq = h + qq * 4;
                const float* Aq = Aa + qq * 4;
                hq[0] = fmaf(__expf(dtv * Aq[0]), hq[0], Bv.x * t);
                hq[1] = fmaf(__expf(dtv * Aq[1]), hq[1], Bv.y * t);
                hq[2] = fmaf(__expf(dtv * Aq[2]), hq[2], Bv.z * t);
                hq[3] = fmaf(__expf(dtv * Aq[3]), hq[3], Bv.w * t);
                y += Cv.x * hq[0] + Cv.y * hq[1] + Cv.z * hq[2] + Cv.w * hq[3];
            }
            y += __shfl_xor_sync(0xffffffffu, y, 1);
            y += __shfl_xor_sync(0xffffffffu, y, 2);
            y += __shfl_xor_sync(0xffffffffu, y, 4);
            if (ns == 0) xp[(size_t)l * DD] = fmaf(Dv, xo, y);
            dtv = dtn; xv = xnn; xo = xon;
        }
        __syncthreads();
    }
}

// ---------------- attention scores: split-K, both batches ----------------
__global__ void __launch_bounds__(128)
attn_scores(const float* __restrict__ A, const float* __restrict__ keys,
            float* __restrict__ part) {
    __shared__ float As[16][64];
    __shared__ float Ws[16][128];
    const int tid = threadIdx.x;
    const int bn = blockIdx.x * 128;
    const int bat = blockIdx.y;
    const int kbase = blockIdx.z * (KDIM / 16);
    const float* W = keys + (size_t)bat * LL * KDIM;
    const int lr = tid >> 2;
    const int lk = (tid & 3) << 2;
    const int tx = tid & 15;
    const int ty = tid >> 4;
    float acc[8][8];
    #pragma unroll
    for (int i = 0; i < 8; i++)
        #pragma unroll
        for (int j = 0; j < 8; j++) acc[i][j] = 0.f;

    for (int k0 = kbase; k0 < kbase + KDIM / 16; k0 += 16) {
        {
            int r = lr;
            float4 v = *(const float4*)(A + (size_t)r * KDIM + k0 + lk);
            As[lk + 0][r] = v.x; As[lk + 1][r] = v.y;
            As[lk + 2][r] = v.z; As[lk + 3][r] = v.w;
            r = lr + 32;
            v = *(const float4*)(A + (size_t)r * KDIM + k0 + lk);
            As[lk + 0][r] = v.x; As[lk + 1][r] = v.y;
            As[lk + 2][r] = v.z; As[lk + 3][r] = v.w;
        }
        #pragma unroll
        for (int hh = 0; hh < 4; hh++) {
            int r = lr + hh * 32;
            float4 v = *(const float4*)(W + (size_t)(bn + r) * KDIM + k0 + lk);
            Ws[lk + 0][r] = v.x; Ws[lk + 1][r] = v.y;
            Ws[lk + 2][r] = v.z; Ws[lk + 3][r] = v.w;
        }
        __syncthreads();
        #pragma unroll
        for (int kk = 0; kk < 16; kk++) {
            float a[8], w[8];
            *(float4*)(a)     = *(const float4*)&As[kk][ty * 8];
            *(float4*)(a + 4) = *(const float4*)&As[kk][ty * 8 + 4];
            *(float4*)(w)     = *(const float4*)&Ws[kk][tx * 8];
            *(float4*)(w + 4) = *(const float4*)&Ws[kk][tx * 8 + 4];
            #pragma unroll
            for (int i = 0; i < 8; i++)
                #pragma unroll
                for (int j = 0; j < 8; j++)
                    acc[i][j] = fmaf(a[i], w[j], acc[i][j]);
        }
        __syncthreads();
    }
    float* outp = part + (size_t)bat * 16 * MM * LL + (size_t)blockIdx.z * MM * LL;
    #pragma unroll
    for (int i = 0; i < 8; i++) {
        int row = ty * 8 + i;
        #pragma unroll
        for (int j4 = 0; j4 < 2; j4++) {
            float4 o = make_float4(acc[i][j4*4+0], acc[i][j4*4+1],
                                   acc[i][j4*4+2], acc[i][j4*4+3]);
            *(float4*)&outp[(size_t)row * LL + bn + tx * 8 + j4 * 4] = o;
        }
    }
}

// fused: sum 16 split-K partials, scale, softmax over 256 cols
__global__ void __launch_bounds__(256)
attn_softmax(const float* __restrict__ part, float* __restrict__ scores,
             float scal) {
    __shared__ float red[8];
    int bx = blockIdx.x;
    int b = bx >> 6, m = bx & 63;
    int l = threadIdx.x;
    const float* p = part + (size_t)b * 16 * MM * LL + (size_t)m * LL + l;
    float s = 0.f;
    #pragma unroll
    for (int z = 0; z < 16; z++) s += p[(size_t)z * MM * LL];
    float v = s * scal;
    float mx = blockReduceMax(v, red);
    float e = __expf(v - mx);
    float sum = blockReduceSum(e, red);
    scores[(size_t)bx * LL + l] = e / sum;
}

// ---------------- mean over L ----------------
__global__ void meanL(const float* __restrict__ xo, float* __restrict__ mean) {
    int idx = blockIdx.x * 256 + threadIdx.x;
    int b = idx / DD, d = idx % DD;
    float s = 0.f;
    for (int l = 0; l < LL; l++) s += xo[(size_t)(b * LL + l) * DD + d];
    mean[idx] = s * (1.f / LL);
}

// ---------------- warp-per-output dot (cond path) ----------
template<int ACT>
__global__ void rowdot(const float* __restrict__ A, const float* __restrict__ W,
                       const float* __restrict__ bias, float* __restrict__ out,
                       int rows, int cols, int K) {
    int gw = (blockIdx.x * blockDim.x + threadIdx.x) >> 5;
    int lane = threadIdx.x & 31;
    if (gw >= rows * cols) return;
    int r = gw / cols, c = gw % cols;
    const float4* a = (const float4*)(A + (size_t)r * K);
    const float4* w = (const float4*)(W + (size_t)c * K);
    int K4 = K >> 2;
    float s = 0.f;
    for (int k = lane; k < K4; k += 32) {
        float4 x = a[k], y = w[k];
        s += x.x * y.x + x.y * y.y + x.z * y.z + x.w * y.w;
    }
    #pragma unroll
    for (int o = 16; o; o >>= 1) s += __shfl_xor_sync(0xffffffffu, s, o);
    if (lane == 0) {
        s += bias[c];
        if (ACT == 2) s = s / (1.f + __expf(-s));
        out[(size_t)r * cols + c] = s;
    }
}

// ---------------- z0 = attn @ values ----------------
__global__ void __launch_bounds__(256)
z0_partial(const float* __restrict__ attn, const float* __restrict__ vals,
           float* __restrict__ part) {
    int d  = blockIdx.x * 256 + threadIdx.x;
    int b  = blockIdx.y;
    int sp = blockIdx.z;
    __shared__ float sa[64][32];
    int l0 = sp * 32;
    for (int i = threadIdx.x; i < 2048; i += 256) {
        int m = i >> 5, li = i & 31;
        sa[m][li] = attn[(size_t)(b * MM + m) * LL + l0 + li];
    }
    __syncthreads();
    float acc[64];
    #pragma unroll
    for (int m = 0; m < 64; m++) acc[m] = 0.f;
    for (int li = 0; li < 32; li += 4) {
        float v0 = vals[(size_t)(b * LL + l0 + li + 0) * DD + d];
        float v1 = vals[(size_t)(b * LL + l0 + li + 1) * DD + d];
        float v2 = vals[(size_t)(b * LL + l0 + li + 2) * DD + d];
        float v3 = vals[(size_t)(b * LL + l0 + li + 3) * DD + d];
        #pragma unroll
        for (int m = 0; m < 64; m++) {
            float4 a4 = *(const float4*)&sa[m][li];
            acc[m] = fmaf(a4.x, v0, fmaf(a4.y, v1, fmaf(a4.z, v2, fmaf(a4.w, v3, acc[m]))));
        }
    }
    #pragma unroll
    for (int m = 0; m < 64; m++)
        part[((size_t)(sp * BATCH + b) * MM + m) * DD + d] = acc[m];
}

__global__ void z0_reduce(const float* __restrict__ part, float* __restrict__ out) {
    int i = blockIdx.x * 256 + threadIdx.x;
    float s = 0.f;
    #pragma unroll
    for (int z = 0; z < 8; z++) s += part[(size_t)z * (BATCH * MM * DD) + i];
    out[i] = s;
}

// ---------------- host side ----------------
extern "C" void kernel_launch(void* const* d_in, const int* in_sizes, int n_in,
                              void* d_out, int out_size) {
    const float* tok  = (const float*)d_in[0];
    const float* ipw  = (const float*)d_in[1];
    const float* ipb  = (const float*)d_in[2];
    const float* ng   = (const float*)d_in[3];
    const float* nb   = (const float*)d_in[4];
    const float* dtw  = (const float*)d_in[5];
    const float* dtb  = (const float*)d_in[6];
    const float* Bw   = (const float*)d_in[7];
    const float* Cw   = (const float*)d_in[8];
    const float* Dvv  = (const float*)d_in[9];
    const float* Alog = (const float*)d_in[10];
    const float* og   = (const float*)d_in[11];
    const float* ob   = (const float*)d_in[12];
    const float* lq   = (const float*)d_in[13];
    const float* pkw  = (const float*)d_in[14];
    const float* pvw  = (const float*)d_in[15];
    const float* w1   = (const float*)d_in[16];
    const float* b1   = (const float*)d_in[17];
    const float* w2   = (const float*)d_in[18];
    const float* b2   = (const float*)d_in[19];
    float* out = (float*)d_out;

    float *px, *pxn, *pdt, *pkeys, *pvals, *pxo, *pBC, *pmean, *pc1, *pscores, *ppart, *pz0p;
    __nv_bfloat16 *piph, *pipl, *pw2h, *pw2l, *pw1h, *pw1l, *pah, *pal;
    cudaGetSymbolAddress((void**)&px,     g_x);
    cudaGetSymbolAddress((void**)&pxn,    g_xn);
    cudaGetSymbolAddress((void**)&pdt,    g_dt);
    cudaGetSymbolAddress((void**)&pkeys,  g_keys);
    cudaGetSymbolAddress((void**)&pvals,  g_vals);
    cudaGetSymbolAddress((void**)&pxo,    g_xo);
    cudaGetSymbolAddress((void**)&pBC,    g_BC);
    cudaGetSymbolAddress((void**)&pmean,  g_mean);
    cudaGetSymbolAddress((void**)&pc1,    g_c1);
    cudaGetSymbolAddress((void**)&pscores,g_scores);
    cudaGetSymbolAddress((void**)&ppart,  g_part);
    cudaGetSymbolAddress((void**)&pz0p,   g_z0p);
    cudaGetSymbolAddress((void**)&piph,   g_ipwh);
    cudaGetSymbolAddress((void**)&pipl,   g_ipwl);
    cudaGetSymbolAddress((void**)&pw2h,   g_w2hi);
    cudaGetSymbolAddress((void**)&pw2l,   g_w2lo);
    cudaGetSymbolAddress((void**)&pw1h,   g_w1hi);
    cudaGetSymbolAddress((void**)&pw1l,   g_w1lo);
    cudaGetSymbolAddress((void**)&pah,    g_ahi);
    cudaGetSymbolAddress((void**)&pal,    g_alo);

    cudaFuncSetAttribute(bf16_gemm<0>, cudaFuncAttributeMaxDynamicSharedMemorySize, SMEM_GEMM);
    cudaFuncSetAttribute(bf16_gemm<1>, cudaFuncAttributeMaxDynamicSharedMemorySize, SMEM_GEMM);

    // second stream (non-blocking) + fork/join events for graph-captured
    // concurrency. Created fresh each call (host-side objects only).
    cudaStream_t s1;
    cudaStreamCreateWithFlags(&s1, cudaStreamNonBlocking);
    cudaEvent_t evA, evB, evC, evD;
    cudaEventCreateWithFlags(&evA, cudaEventDisableTiming);
    cudaEventCreateWithFlags(&evB, cudaEventDisableTiming);
    cudaEventCreateWithFlags(&evC, cudaEventDisableTiming);
    cudaEventCreateWithFlags(&evD, cudaEventDisableTiming);

    // 1) split tok+ipw on main stream
    split_ip<<<(int)((NIPQ + 255) / 256), 256>>>(tok, ipw, pah, pal, piph, pipl);
    // fork: big weight split runs on s1 concurrently with ip GEMM + ln
    cudaEventRecord(evA, 0);
    cudaStreamWaitEvent(s1, evA, 0);
    split_rest<<<(int)((NRQ + 255) / 256), 256, 0, s1>>>(dtw, Bw, Cw, pkw, pvw,
                                                         pw2h, pw2l, pw1h, pw1l);
    cudaEventRecord(evB, s1);

    // main: input projection + layer-0 layernorm
    bf16_gemm<0><<<dim3(28, 4), GTHR, SMEM_GEMM>>>(pah, pal, piph, pipl,
                                                   ipb, px, nullptr, 28, 0);
    ln_split<<<BL, 256>>>(px, ng, nb, pxn, pah, pal);

    // join: dtBC GEMM needs the w2 split
    cudaStreamWaitEvent(0, evB, 0);
    bf16_gemm<1><<<dim3(29, 4), GTHR, SMEM_GEMM>>>(pah, pal, pw2h, pw2l,
                                                   dtb, pdt, pBC, 28, 128);
    scan_kernel<<<dim3(DD / SCD, BATCH), SCD * 8>>>(pxn, pdt, pBC, Alog, Dvv, px);
    // layer 1
    ln_split<<<BL, 256>>>(px, ng + DD, nb + DD, pxn, pah, pal);
    bf16_gemm<1><<<dim3(29, 4), GTHR, SMEM_GEMM>>>(pah, pal,
                                                   pw2h + (size_t)3712 * KDIM,
                                                   pw2l + (size_t)3712 * KDIM,
                                                   dtb + DD, pdt, pBC, 28, 128);
    scan_kernel<<<dim3(DD / SCD, BATCH), SCD * 8>>>(pxn, pdt, pBC,
                                                    Alog + (size_t)DD * NST,
                                                    Dvv + DD, px);
    // output norm (+ split for pooling GEMM)
    ln_split<<<BL, 256>>>(px, og, ob, pxo, pah, pal);

    // fork: conditioning head on s1, concurrent with pkv GEMM
    cudaEventRecord(evC, 0);
    cudaStreamWaitEvent(s1, evC, 0);
    meanL<<<(BATCH * DD) / 256, 256, 0, s1>>>(pxo, pmean);
    rowdot<2><<<(BATCH * CONDD * 32 + 255) / 256, 256, 0, s1>>>(pmean, w1, b1, pc1,
                                                                BATCH, CONDD, DD);
    rowdot<0><<<(BATCH * CONDD * 32 + 255) / 256, 256, 0, s1>>>(pc1, w2, b2,
                                                                out + BATCH * MM * DD,
                                                                BATCH, CONDD, CONDD);
    cudaEventRecord(evD, s1);

    // main: fused pool_k | pool_v projection (N = 7168)
    bf16_gemm<0><<<dim3(56, 4), GTHR, SMEM_GEMM>>>(pah, pal, pw1h, pw1l,
                                                   nullptr, pkeys, pvals, 28, DD);

    // attention + z0 on main
    attn_scores<<<dim3(LL / 128, BATCH, 16), 128>>>(lq, pkeys, ppart);
    attn_softmax<<<BATCH * MM, 256>>>(ppart, pscores, 1.f / sqrtf((float)DD));
    z0_partial<<<dim3(DD / 256, BATCH, 8), 256>>>(pscores, pvals, pz0p);
    z0_reduce<<<(BATCH * MM * DD) / 256, 256>>>(pz0p, out);

    // join cond-head fork back to origin stream before returning
    cudaStreamWaitEvent(0, evD, 0);
}